// round 7
// baseline (speedup 1.0000x reference)
#include <cuda_runtime.h>
#include <cstdint>

// Problem constants (stagenet_46445776339346): V=5, B=2, C=32, H=W=128, D=32, G=8
#define NV 5
#define NB 2
#define NC 32
#define NH 128
#define NW 128
#define ND 32
#define NG 8
#define HW (NH * NW)

// ---------------------------------------------------------------------------
// Device scratch (no runtime allocation allowed)
// ---------------------------------------------------------------------------
__device__ float  g_rot[NB][NV][9];
__device__ float  g_trans[NB][NV][3];
// features transposed to [V, B, H*W, C]: one bilinear tap = 128 contiguous bytes.
__device__ float4 g_featT[(size_t)NV * NB * HW * (NC / 4)];

// ---------------------------------------------------------------------------
// FROZEN NUMERICS: fp32 4x4 inverse = sgetf2 LU (reciprocal scal) +
// lu_solve(identity) with OpenBLAS-style trsm (pre-inverted diagonal,
// reciprocal multiply). This made the bench pass — do not touch.
// ---------------------------------------------------------------------------
__device__ void inv4_lapack_f32(const float* A_rm /*row-major 16*/, float* Ai_rm) {
    float a[16];   // column-major: a[c*4+r]
    int   piv[4];
#pragma unroll
    for (int r = 0; r < 4; r++)
#pragma unroll
        for (int c = 0; c < 4; c++) a[c * 4 + r] = A_rm[r * 4 + c];

#pragma unroll
    for (int j = 0; j < 4; j++) {
        int jp = j; float amax = fabsf(a[j * 4 + j]);
        for (int i = j + 1; i < 4; i++) {
            float v = fabsf(a[j * 4 + i]);
            if (v > amax) { amax = v; jp = i; }
        }
        piv[j] = jp;
        if (jp != j)
#pragma unroll
            for (int c = 0; c < 4; c++) {
                float t = a[c * 4 + j]; a[c * 4 + j] = a[c * 4 + jp]; a[c * 4 + jp] = t;
            }
        float ainv = __fdiv_rn(1.0f, a[j * 4 + j]);
        for (int i = j + 1; i < 4; i++)
            a[j * 4 + i] = __fmul_rn(a[j * 4 + i], ainv);
        for (int k = j + 1; k < 4; k++) {
            float temp = -a[k * 4 + j];
            for (int i = j + 1; i < 4; i++)
                a[k * 4 + i] = fmaf(a[j * 4 + i], temp, a[k * 4 + i]);
        }
    }

    float dinv[4];
#pragma unroll
    for (int k = 0; k < 4; k++) dinv[k] = __fdiv_rn(1.0f, a[k * 4 + k]);

#pragma unroll
    for (int c = 0; c < 4; c++) {
        float b[4] = {0.f, 0.f, 0.f, 0.f};
        b[c] = 1.0f;
#pragma unroll
        for (int j = 0; j < 4; j++) { float t = b[j]; b[j] = b[piv[j]]; b[piv[j]] = t; }
#pragma unroll
        for (int k = 0; k < 4; k++) {
            float bk = b[k];
            if (bk != 0.f)
                for (int i = k + 1; i < 4; i++)
                    b[i] = fmaf(-bk, a[k * 4 + i], b[i]);
        }
#pragma unroll
        for (int k = 3; k >= 0; k--) {
            b[k] = __fmul_rn(b[k], dinv[k]);
            float bk = b[k];
            for (int i = 0; i < k; i++)
                b[i] = fmaf(-bk, a[k * 4 + i], b[i]);
        }
#pragma unroll
        for (int r = 0; r < 4; r++) Ai_rm[r * 4 + c] = b[r];
    }
}

__device__ void make_comb_f32(const float* pm, int b, int v, float* M /*16 rm*/) {
    const float* ext = pm + ((size_t)(b * NV + v) * 2 + 0) * 16;
    const float* K   = pm + ((size_t)(b * NV + v) * 2 + 1) * 16;
#pragma unroll
    for (int r = 0; r < 3; r++)
#pragma unroll
        for (int c = 0; c < 4; c++) {
            float s = __fmul_rn(K[r * 4 + 0], ext[0 * 4 + c]);
            s = fmaf(K[r * 4 + 1], ext[1 * 4 + c], s);
            s = fmaf(K[r * 4 + 2], ext[2 * 4 + c], s);
            M[r * 4 + c] = s;
        }
#pragma unroll
    for (int c = 0; c < 4; c++) M[12 + c] = ext[12 + c];
}

__device__ void do_setup(const float* pm, int b) {
    float Mr[16], Mi[16];
    make_comb_f32(pm, b, 0, Mr);
    inv4_lapack_f32(Mr, Mi);
    for (int v = 1; v < NV; v++) {
        float Ms[16];
        make_comb_f32(pm, b, v, Ms);
        for (int r = 0; r < 3; r++) {
            for (int c = 0; c < 4; c++) {
                float s = __fmul_rn(Ms[r * 4 + 0], Mi[0 * 4 + c]);
                s = fmaf(Ms[r * 4 + 1], Mi[1 * 4 + c], s);
                s = fmaf(Ms[r * 4 + 2], Mi[2 * 4 + c], s);
                s = fmaf(Ms[r * 4 + 3], Mi[3 * 4 + c], s);
                if (c < 3) g_rot[b][v][r * 3 + c] = s;
                else       g_trans[b][v][r] = s;
            }
        }
    }
}

// ---------------------------------------------------------------------------
// Prep kernel: feature transpose [V*B, C, HW] -> [V*B, HW, C], plus the
// projection-matrix setup on 2 threads of block (0,0) (overlapped with the
// transpose traffic of all other blocks).
// ---------------------------------------------------------------------------
__global__ void prep_kernel(const float* __restrict__ fea,
                            const float* __restrict__ pm) {
    __shared__ float tile[32][33];
    int vb = blockIdx.y;
    int pb = blockIdx.x * 32;
    int tx = threadIdx.x, ty = threadIdx.y;

    if (blockIdx.x == 0 && blockIdx.y == 0 && ty == 1 && tx < NB)
        do_setup(pm, tx);

    tile[ty][tx] = fea[(size_t)vb * NC * HW + (size_t)ty * HW + pb + tx];
    __syncthreads();
    ((float*)g_featT)[((size_t)vb * HW + pb + ty) * NC + tx] = tile[tx][ty];
}

// ---------------------------------------------------------------------------
// Butterfly warp sum (order-independent tree; numerics spend vs seq order,
// covered by 6x rel_err margin).
// ---------------------------------------------------------------------------
__device__ __forceinline__ float warp_bfly_sum(float x) {
    const unsigned FULL = 0xffffffffu;
#pragma unroll
    for (int o = 16; o; o >>= 1) x = __fadd_rn(x, __shfl_xor_sync(FULL, x, o));
    return x;
}

// ---------------------------------------------------------------------------
// Main kernel: one warp per ref pixel, lane = depth hypothesis.
// ---------------------------------------------------------------------------
__global__ void __launch_bounds__(256) stagenet_main(
    const float* __restrict__ depth_hypo,
    const float* __restrict__ reg_w,
    float* __restrict__ out) {
    const unsigned FULL = 0xffffffffu;
    int warp = blockIdx.x * (blockDim.x >> 5) + (threadIdx.x >> 5);
    int lane = threadIdx.x & 31;

    int b  = warp >> 14;
    int hw = warp & (HW - 1);
    int h  = hw >> 7;
    int w  = hw & (NW - 1);

    const float4* refp = g_featT + ((size_t)b * HW + hw) * 8;   // view 0
    float4 rf[8];
#pragma unroll
    for (int j = 0; j < 8; j++) rf[j] = __ldg(refp + j);

    float dep = depth_hypo[((size_t)(b * ND + lane)) * HW + hw];
    float xw = (float)w, yh = (float)h;

    float acc[8];
#pragma unroll
    for (int j = 0; j < 8; j++) acc[j] = 0.f;
    float cw_sum = 1e-8f;

#pragma unroll
    for (int v = 1; v < NV; v++) {
        const float* R = g_rot[b][v];
        const float* T = g_trans[b][v];
        // rot @ [x, y, 1]: fma chain, ascending k (frozen form)
        float rx = fmaf(R[2], 1.f, fmaf(R[1], yh, __fmul_rn(R[0], xw)));
        float ry = fmaf(R[5], 1.f, fmaf(R[4], yh, __fmul_rn(R[3], xw)));
        float rz = fmaf(R[8], 1.f, fmaf(R[7], yh, __fmul_rn(R[6], xw)));
        // elementwise: separate mul/add (frozen)
        float X = __fadd_rn(__fmul_rn(rx, dep), T[0]);
        float Y = __fadd_rn(__fmul_rn(ry, dep), T[1]);
        float Z = __fadd_rn(__fmul_rn(rz, dep), T[2]);
        if (Z == 0.f) Z = 1e-9f;
        float px = __fdiv_rn(X, Z);
        float py = __fdiv_rn(Y, Z);

        float x0f = floorf(px), y0f = floorf(py);
        int   x0 = (int)x0f,   y0 = (int)y0f;
        float wx1 = __fsub_rn(px, x0f), wx0 = __fsub_rn(1.f, wx1);
        float wy1 = __fsub_rn(py, y0f), wy0 = __fsub_rn(1.f, wy1);

        // Branchless taps: clamp index, zero weight if OOB.
        int x0c = min(max(x0, 0), NW - 1), x1c = min(max(x0 + 1, 0), NW - 1);
        int y0c = min(max(y0, 0), NH - 1), y1c = min(max(y0 + 1, 0), NH - 1);
        bool vx0 = (x0 >= 0) & (x0 < NW),     vx1 = (x0 + 1 >= 0) & (x0 + 1 < NW);
        bool vy0 = (y0 >= 0) & (y0 < NH),     vy1 = (y0 + 1 >= 0) & (y0 + 1 < NH);
        float wts[4] = {
            (vx0 & vy0) ? __fmul_rn(wx0, wy0) : 0.f,
            (vx1 & vy0) ? __fmul_rn(wx1, wy0) : 0.f,
            (vx0 & vy1) ? __fmul_rn(wx0, wy1) : 0.f,
            (vx1 & vy1) ? __fmul_rn(wx1, wy1) : 0.f };
        const float4* base = g_featT + ((size_t)(v * NB + b) * HW) * 8;
        const float4* tp[4] = {
            base + (size_t)(y0c * NW + x0c) * 8,
            base + (size_t)(y0c * NW + x1c) * 8,
            base + (size_t)(y1c * NW + x0c) * 8,
            base + (size_t)(y1c * NW + x1c) * 8 };

        float pg[8];
#pragma unroll
        for (int g = 0; g < 8; g++) pg[g] = 0.f;
#pragma unroll
        for (int t = 0; t < 4; t++) {
            float wt = wts[t];
#pragma unroll
            for (int g = 0; g < 8; g++) {
                float4 q = __ldg(tp[t] + g);
                float d = fmaf(q.x, rf[g].x,
                          fmaf(q.y, rf[g].y,
                          fmaf(q.z, rf[g].z, __fmul_rn(q.w, rf[g].w))));
                pg[g] = fmaf(wt, d, pg[g]);
            }
        }

        float cf[8];
        float s = 0.f;
#pragma unroll
        for (int g = 0; g < 8; g++) {
            cf[g] = __fmul_rn(pg[g], 0.25f);
            s = (g == 0) ? cf[0] : __fadd_rn(s, cf[g]);
        }

        // softmax over depth lanes (butterfly reductions)
        float m = s;
#pragma unroll
        for (int o = 16; o; o >>= 1) m = fmaxf(m, __shfl_xor_sync(FULL, m, o));
        float e = expf(__fsub_rn(s, m));
        float es = warp_bfly_sum(e);
        float wv = __fmul_rn(__fdiv_rn(e, es), 0.17677669529663687f);  // 1/sqrt(32)

        cw_sum = __fadd_rn(cw_sum, wv);
#pragma unroll
        for (int g = 0; g < 8; g++)
            acc[g] = fmaf(wv, cf[g], acc[g]);
    }

    // cor_feats / cor_weight_sum, then reg_w contraction (fma chain)
    float logit = 0.f;
#pragma unroll
    for (int g = 0; g < 8; g++) {
        float vgl = __fdiv_rn(acc[g], cw_sum);
        float rw  = __ldg(reg_w + g);
        logit = (g == 0) ? __fmul_rn(rw, vgl) : fmaf(rw, vgl, logit);
    }

    // final softmax over depth (butterfly)
    float m2 = logit;
#pragma unroll
    for (int o = 16; o; o >>= 1) m2 = fmaxf(m2, __shfl_xor_sync(FULL, m2, o));
    float e2 = expf(__fsub_rn(logit, m2));
    float es2 = warp_bfly_sum(e2);
    float attn = __fdiv_rn(e2, es2);

    // outputs: [depth (B*H*W)] then [attn (B*D*H*W)]
    out[(size_t)NB * HW + ((size_t)(b * ND + lane)) * HW + hw] = attn;

    float amax = attn;
#pragma unroll
    for (int o = 16; o; o >>= 1) amax = fmaxf(amax, __shfl_xor_sync(FULL, amax, o));
    unsigned msk = __ballot_sync(FULL, attn == amax);
    int idx = __ffs(msk) - 1;   // first max, matching jnp.argmax
    if (lane == idx) out[(size_t)b * HW + hw] = dep;
}

// ---------------------------------------------------------------------------
// Launch
// ---------------------------------------------------------------------------
extern "C" void kernel_launch(void* const* d_in, const int* in_sizes, int n_in,
                              void* d_out, int out_size) {
    const float* features   = (const float*)d_in[0];
    const float* proj       = (const float*)d_in[1];
    const float* depth_hypo = (const float*)d_in[2];
    const float* reg_w      = (const float*)d_in[3];
    float* out = (float*)d_out;

    prep_kernel<<<dim3(HW / 32, NV * NB), dim3(32, 32)>>>(features, proj);
    stagenet_main<<<(NB * HW) / 8, 256>>>(depth_hypo, reg_w, out);
}

// round 8
// speedup vs baseline: 1.3311x; 1.3311x over previous
#include <cuda_runtime.h>
#include <cstdint>

// Problem constants (stagenet_46445776339346): V=5, B=2, C=32, H=W=128, D=32, G=8
#define NV 5
#define NB 2
#define NC 32
#define NH 128
#define NW 128
#define ND 32
#define NG 8
#define HW (NH * NW)

// ---------------------------------------------------------------------------
// Device scratch (no runtime allocation allowed)
// ---------------------------------------------------------------------------
__device__ float  g_rot[NB][NV][9];
__device__ float  g_trans[NB][NV][3];
// features transposed to [V, B, H*W, C]: one bilinear tap = 128 contiguous bytes.
__device__ float4 g_featT[(size_t)NV * NB * HW * (NC / 4)];

// ---------------------------------------------------------------------------
// FROZEN NUMERICS: fp32 4x4 inverse = sgetf2 LU (reciprocal scal) +
// lu_solve(identity) with OpenBLAS-style trsm (pre-inverted diagonal,
// reciprocal multiply). This made the bench pass — do not touch.
// ---------------------------------------------------------------------------
__device__ void inv4_lapack_f32(const float* A_rm /*row-major 16*/, float* Ai_rm) {
    float a[16];   // column-major: a[c*4+r]
    int   piv[4];
#pragma unroll
    for (int r = 0; r < 4; r++)
#pragma unroll
        for (int c = 0; c < 4; c++) a[c * 4 + r] = A_rm[r * 4 + c];

#pragma unroll
    for (int j = 0; j < 4; j++) {
        int jp = j; float amax = fabsf(a[j * 4 + j]);
        for (int i = j + 1; i < 4; i++) {
            float v = fabsf(a[j * 4 + i]);
            if (v > amax) { amax = v; jp = i; }
        }
        piv[j] = jp;
        if (jp != j)
#pragma unroll
            for (int c = 0; c < 4; c++) {
                float t = a[c * 4 + j]; a[c * 4 + j] = a[c * 4 + jp]; a[c * 4 + jp] = t;
            }
        float ainv = __fdiv_rn(1.0f, a[j * 4 + j]);
        for (int i = j + 1; i < 4; i++)
            a[j * 4 + i] = __fmul_rn(a[j * 4 + i], ainv);
        for (int k = j + 1; k < 4; k++) {
            float temp = -a[k * 4 + j];
            for (int i = j + 1; i < 4; i++)
                a[k * 4 + i] = fmaf(a[j * 4 + i], temp, a[k * 4 + i]);
        }
    }

    float dinv[4];
#pragma unroll
    for (int k = 0; k < 4; k++) dinv[k] = __fdiv_rn(1.0f, a[k * 4 + k]);

#pragma unroll
    for (int c = 0; c < 4; c++) {
        float b[4] = {0.f, 0.f, 0.f, 0.f};
        b[c] = 1.0f;
#pragma unroll
        for (int j = 0; j < 4; j++) { float t = b[j]; b[j] = b[piv[j]]; b[piv[j]] = t; }
#pragma unroll
        for (int k = 0; k < 4; k++) {
            float bk = b[k];
            if (bk != 0.f)
                for (int i = k + 1; i < 4; i++)
                    b[i] = fmaf(-bk, a[k * 4 + i], b[i]);
        }
#pragma unroll
        for (int k = 3; k >= 0; k--) {
            b[k] = __fmul_rn(b[k], dinv[k]);
            float bk = b[k];
            for (int i = 0; i < k; i++)
                b[i] = fmaf(-bk, a[k * 4 + i], b[i]);
        }
#pragma unroll
        for (int r = 0; r < 4; r++) Ai_rm[r * 4 + c] = b[r];
    }
}

__device__ void make_comb_f32(const float* pm, int b, int v, float* M /*16 rm*/) {
    const float* ext = pm + ((size_t)(b * NV + v) * 2 + 0) * 16;
    const float* K   = pm + ((size_t)(b * NV + v) * 2 + 1) * 16;
#pragma unroll
    for (int r = 0; r < 3; r++)
#pragma unroll
        for (int c = 0; c < 4; c++) {
            float s = __fmul_rn(K[r * 4 + 0], ext[0 * 4 + c]);
            s = fmaf(K[r * 4 + 1], ext[1 * 4 + c], s);
            s = fmaf(K[r * 4 + 2], ext[2 * 4 + c], s);
            M[r * 4 + c] = s;
        }
#pragma unroll
    for (int c = 0; c < 4; c++) M[12 + c] = ext[12 + c];
}

__device__ void do_setup(const float* pm, int b) {
    float Mr[16], Mi[16];
    make_comb_f32(pm, b, 0, Mr);
    inv4_lapack_f32(Mr, Mi);
    for (int v = 1; v < NV; v++) {
        float Ms[16];
        make_comb_f32(pm, b, v, Ms);
        for (int r = 0; r < 3; r++) {
            for (int c = 0; c < 4; c++) {
                float s = __fmul_rn(Ms[r * 4 + 0], Mi[0 * 4 + c]);
                s = fmaf(Ms[r * 4 + 1], Mi[1 * 4 + c], s);
                s = fmaf(Ms[r * 4 + 2], Mi[2 * 4 + c], s);
                s = fmaf(Ms[r * 4 + 3], Mi[3 * 4 + c], s);
                if (c < 3) g_rot[b][v][r * 3 + c] = s;
                else       g_trans[b][v][r] = s;
            }
        }
    }
}

// ---------------------------------------------------------------------------
// Prep kernel: feature transpose + projection setup (overlapped).
// ---------------------------------------------------------------------------
__global__ void prep_kernel(const float* __restrict__ fea,
                            const float* __restrict__ pm) {
    __shared__ float tile[32][33];
    int vb = blockIdx.y;
    int pb = blockIdx.x * 32;
    int tx = threadIdx.x, ty = threadIdx.y;

    if (blockIdx.x == 0 && blockIdx.y == 0 && ty == 1 && tx < NB)
        do_setup(pm, tx);

    tile[ty][tx] = fea[(size_t)vb * NC * HW + (size_t)ty * HW + pb + tx];
    __syncthreads();
    ((float*)g_featT)[((size_t)vb * HW + pb + ty) * NC + tx] = tile[tx][ty];
}

// ---------------------------------------------------------------------------
// Butterfly warp sum (validated: rel_err 1.16e-4 in R7).
// ---------------------------------------------------------------------------
__device__ __forceinline__ float warp_bfly_sum(float x) {
    const unsigned FULL = 0xffffffffu;
#pragma unroll
    for (int o = 16; o; o >>= 1) x = __fadd_rn(x, __shfl_xor_sync(FULL, x, o));
    return x;
}

// ---------------------------------------------------------------------------
// Main kernel: one warp per ref pixel, lane = depth hypothesis.
// 128-thread blocks: 94-reg kernel fits 5 blocks/SM -> 20 warps (31% occ)
// vs 16 warps with 256-thread blocks. Latency-bound kernel -> direct win.
// ---------------------------------------------------------------------------
__global__ void __launch_bounds__(128, 5) stagenet_main(
    const float* __restrict__ depth_hypo,
    const float* __restrict__ reg_w,
    float* __restrict__ out) {
    const unsigned FULL = 0xffffffffu;
    int warp = blockIdx.x * (blockDim.x >> 5) + (threadIdx.x >> 5);
    int lane = threadIdx.x & 31;

    int b  = warp >> 14;
    int hw = warp & (HW - 1);
    int h  = hw >> 7;
    int w  = hw & (NW - 1);

    const float4* refp = g_featT + ((unsigned)b * HW + hw) * 8;   // view 0
    float4 rf[8];
#pragma unroll
    for (int j = 0; j < 8; j++) rf[j] = __ldg(refp + j);

    float dep = depth_hypo[(unsigned)(b * ND + lane) * HW + hw];
    float xw = (float)w, yh = (float)h;

    float acc[8];
#pragma unroll
    for (int j = 0; j < 8; j++) acc[j] = 0.f;
    float cw_sum = 1e-8f;

#pragma unroll
    for (int v = 1; v < NV; v++) {
        const float* R = g_rot[b][v];
        const float* T = g_trans[b][v];
        // rot @ [x, y, 1]: fma chain, ascending k (frozen form)
        float rx = fmaf(R[2], 1.f, fmaf(R[1], yh, __fmul_rn(R[0], xw)));
        float ry = fmaf(R[5], 1.f, fmaf(R[4], yh, __fmul_rn(R[3], xw)));
        float rz = fmaf(R[8], 1.f, fmaf(R[7], yh, __fmul_rn(R[6], xw)));
        // elementwise: separate mul/add (frozen)
        float X = __fadd_rn(__fmul_rn(rx, dep), T[0]);
        float Y = __fadd_rn(__fmul_rn(ry, dep), T[1]);
        float Z = __fadd_rn(__fmul_rn(rz, dep), T[2]);
        if (Z == 0.f) Z = 1e-9f;
        float px = __fdiv_rn(X, Z);
        float py = __fdiv_rn(Y, Z);

        float x0f = floorf(px), y0f = floorf(py);
        int   x0 = (int)x0f,   y0 = (int)y0f;
        float wx1 = __fsub_rn(px, x0f), wx0 = __fsub_rn(1.f, wx1);
        float wy1 = __fsub_rn(py, y0f), wy0 = __fsub_rn(1.f, wy1);

        // Branchless taps: clamp index, zero weight if OOB.
        int x0c = min(max(x0, 0), NW - 1), x1c = min(max(x0 + 1, 0), NW - 1);
        int y0c = min(max(y0, 0), NH - 1), y1c = min(max(y0 + 1, 0), NH - 1);
        bool vx0 = (x0 >= 0) & (x0 < NW),     vx1 = (x0 + 1 >= 0) & (x0 + 1 < NW);
        bool vy0 = (y0 >= 0) & (y0 < NH),     vy1 = (y0 + 1 >= 0) & (y0 + 1 < NH);
        float wts[4] = {
            (vx0 & vy0) ? __fmul_rn(wx0, wy0) : 0.f,
            (vx1 & vy0) ? __fmul_rn(wx1, wy0) : 0.f,
            (vx0 & vy1) ? __fmul_rn(wx0, wy1) : 0.f,
            (vx1 & vy1) ? __fmul_rn(wx1, wy1) : 0.f };
        // 32-bit element offsets; single 64-bit extend at access.
        const float4* base = g_featT + (unsigned)(v * NB + b) * (HW * 8u);
        unsigned off[4] = {
            (unsigned)(y0c * NW + x0c) * 8u,
            (unsigned)(y0c * NW + x1c) * 8u,
            (unsigned)(y1c * NW + x0c) * 8u,
            (unsigned)(y1c * NW + x1c) * 8u };

        float pg[8];
#pragma unroll
        for (int g = 0; g < 8; g++) pg[g] = 0.f;
#pragma unroll
        for (int t = 0; t < 4; t++) {
            float wt = wts[t];
            const float4* tp = base + off[t];
#pragma unroll
            for (int g = 0; g < 8; g++) {
                float4 q = __ldg(tp + g);
                float d = fmaf(q.x, rf[g].x,
                          fmaf(q.y, rf[g].y,
                          fmaf(q.z, rf[g].z, __fmul_rn(q.w, rf[g].w))));
                pg[g] = fmaf(wt, d, pg[g]);
            }
        }

        float cf[8];
        float s = 0.f;
#pragma unroll
        for (int g = 0; g < 8; g++) {
            cf[g] = __fmul_rn(pg[g], 0.25f);
            s = (g == 0) ? cf[0] : __fadd_rn(s, cf[g]);
        }

        // softmax over depth lanes
        float m = s;
#pragma unroll
        for (int o = 16; o; o >>= 1) m = fmaxf(m, __shfl_xor_sync(FULL, m, o));
        float e = expf(__fsub_rn(s, m));
        float es = warp_bfly_sum(e);
        float wv = __fmul_rn(__fdiv_rn(e, es), 0.17677669529663687f);  // 1/sqrt(32)

        cw_sum = __fadd_rn(cw_sum, wv);
#pragma unroll
        for (int g = 0; g < 8; g++)
            acc[g] = fmaf(wv, cf[g], acc[g]);
    }

    // cor_feats / cor_weight_sum, then reg_w contraction (fma chain)
    float logit = 0.f;
#pragma unroll
    for (int g = 0; g < 8; g++) {
        float vgl = __fdiv_rn(acc[g], cw_sum);
        float rw  = __ldg(reg_w + g);
        logit = (g == 0) ? __fmul_rn(rw, vgl) : fmaf(rw, vgl, logit);
    }

    // final softmax over depth
    float m2 = logit;
#pragma unroll
    for (int o = 16; o; o >>= 1) m2 = fmaxf(m2, __shfl_xor_sync(FULL, m2, o));
    float e2 = expf(__fsub_rn(logit, m2));
    float es2 = warp_bfly_sum(e2);
    float attn = __fdiv_rn(e2, es2);

    // outputs: [depth (B*H*W)] then [attn (B*D*H*W)]
    out[(unsigned)NB * HW + (unsigned)(b * ND + lane) * HW + hw] = attn;

    float amax = attn;
#pragma unroll
    for (int o = 16; o; o >>= 1) amax = fmaxf(amax, __shfl_xor_sync(FULL, amax, o));
    unsigned msk = __ballot_sync(FULL, attn == amax);
    int idx = __ffs(msk) - 1;   // first max, matching jnp.argmax
    if (lane == idx) out[(unsigned)b * HW + hw] = dep;
}

// ---------------------------------------------------------------------------
// Launch
// ---------------------------------------------------------------------------
extern "C" void kernel_launch(void* const* d_in, const int* in_sizes, int n_in,
                              void* d_out, int out_size) {
    const float* features   = (const float*)d_in[0];
    const float* proj       = (const float*)d_in[1];
    const float* depth_hypo = (const float*)d_in[2];
    const float* reg_w      = (const float*)d_in[3];
    float* out = (float*)d_out;

    prep_kernel<<<dim3(HW / 32, NV * NB), dim3(32, 32)>>>(features, proj);
    stagenet_main<<<(NB * HW) / 4, 128>>>(depth_hypo, reg_w, out);
}

// round 9
// speedup vs baseline: 1.4768x; 1.1095x over previous
#include <cuda_runtime.h>
#include <cstdint>

// Problem constants (stagenet_46445776339346): V=5, B=2, C=32, H=W=128, D=32, G=8
#define NV 5
#define NB 2
#define NC 32
#define NH 128
#define NW 128
#define ND 32
#define NG 8
#define HW (NH * NW)

// ---------------------------------------------------------------------------
// Device scratch (no runtime allocation allowed)
// ---------------------------------------------------------------------------
__device__ float  g_rot[NB][NV][9];
__device__ float  g_trans[NB][NV][3];
// features transposed to [V, B, H*W, C]: one bilinear tap = 128 contiguous bytes.
__device__ float4 g_featT[(size_t)NV * NB * HW * (NC / 4)];

// ---------------------------------------------------------------------------
// FROZEN NUMERICS: fp32 4x4 inverse = sgetf2 LU + OpenBLAS-style trsm
// (pre-inverted diagonal). Do not touch.
// ---------------------------------------------------------------------------
__device__ void inv4_lapack_f32(const float* A_rm, float* Ai_rm) {
    float a[16];
    int   piv[4];
#pragma unroll
    for (int r = 0; r < 4; r++)
#pragma unroll
        for (int c = 0; c < 4; c++) a[c * 4 + r] = A_rm[r * 4 + c];

#pragma unroll
    for (int j = 0; j < 4; j++) {
        int jp = j; float amax = fabsf(a[j * 4 + j]);
        for (int i = j + 1; i < 4; i++) {
            float v = fabsf(a[j * 4 + i]);
            if (v > amax) { amax = v; jp = i; }
        }
        piv[j] = jp;
        if (jp != j)
#pragma unroll
            for (int c = 0; c < 4; c++) {
                float t = a[c * 4 + j]; a[c * 4 + j] = a[c * 4 + jp]; a[c * 4 + jp] = t;
            }
        float ainv = __fdiv_rn(1.0f, a[j * 4 + j]);
        for (int i = j + 1; i < 4; i++)
            a[j * 4 + i] = __fmul_rn(a[j * 4 + i], ainv);
        for (int k = j + 1; k < 4; k++) {
            float temp = -a[k * 4 + j];
            for (int i = j + 1; i < 4; i++)
                a[k * 4 + i] = fmaf(a[j * 4 + i], temp, a[k * 4 + i]);
        }
    }

    float dinv[4];
#pragma unroll
    for (int k = 0; k < 4; k++) dinv[k] = __fdiv_rn(1.0f, a[k * 4 + k]);

#pragma unroll
    for (int c = 0; c < 4; c++) {
        float b[4] = {0.f, 0.f, 0.f, 0.f};
        b[c] = 1.0f;
#pragma unroll
        for (int j = 0; j < 4; j++) { float t = b[j]; b[j] = b[piv[j]]; b[piv[j]] = t; }
#pragma unroll
        for (int k = 0; k < 4; k++) {
            float bk = b[k];
            if (bk != 0.f)
                for (int i = k + 1; i < 4; i++)
                    b[i] = fmaf(-bk, a[k * 4 + i], b[i]);
        }
#pragma unroll
        for (int k = 3; k >= 0; k--) {
            b[k] = __fmul_rn(b[k], dinv[k]);
            float bk = b[k];
            for (int i = 0; i < k; i++)
                b[i] = fmaf(-bk, a[k * 4 + i], b[i]);
        }
#pragma unroll
        for (int r = 0; r < 4; r++) Ai_rm[r * 4 + c] = b[r];
    }
}

__device__ void make_comb_f32(const float* pm, int b, int v, float* M) {
    const float* ext = pm + ((size_t)(b * NV + v) * 2 + 0) * 16;
    const float* K   = pm + ((size_t)(b * NV + v) * 2 + 1) * 16;
#pragma unroll
    for (int r = 0; r < 3; r++)
#pragma unroll
        for (int c = 0; c < 4; c++) {
            float s = __fmul_rn(K[r * 4 + 0], ext[0 * 4 + c]);
            s = fmaf(K[r * 4 + 1], ext[1 * 4 + c], s);
            s = fmaf(K[r * 4 + 2], ext[2 * 4 + c], s);
            M[r * 4 + c] = s;
        }
#pragma unroll
    for (int c = 0; c < 4; c++) M[12 + c] = ext[12 + c];
}

__device__ void do_setup(const float* pm, int b) {
    float Mr[16], Mi[16];
    make_comb_f32(pm, b, 0, Mr);
    inv4_lapack_f32(Mr, Mi);
    for (int v = 1; v < NV; v++) {
        float Ms[16];
        make_comb_f32(pm, b, v, Ms);
        for (int r = 0; r < 3; r++) {
            for (int c = 0; c < 4; c++) {
                float s = __fmul_rn(Ms[r * 4 + 0], Mi[0 * 4 + c]);
                s = fmaf(Ms[r * 4 + 1], Mi[1 * 4 + c], s);
                s = fmaf(Ms[r * 4 + 2], Mi[2 * 4 + c], s);
                s = fmaf(Ms[r * 4 + 3], Mi[3 * 4 + c], s);
                if (c < 3) g_rot[b][v][r * 3 + c] = s;
                else       g_trans[b][v][r] = s;
            }
        }
    }
}

// ---------------------------------------------------------------------------
// Prep kernel: feature transpose + projection setup (overlapped).
// ---------------------------------------------------------------------------
__global__ void prep_kernel(const float* __restrict__ fea,
                            const float* __restrict__ pm) {
    __shared__ float tile[32][33];
    int vb = blockIdx.y;
    int pb = blockIdx.x * 32;
    int tx = threadIdx.x, ty = threadIdx.y;

    if (blockIdx.x == 0 && blockIdx.y == 0 && ty == 1 && tx < NB)
        do_setup(pm, tx);

    tile[ty][tx] = fea[(size_t)vb * NC * HW + (size_t)ty * HW + pb + tx];
    __syncthreads();
    ((float*)g_featT)[((size_t)vb * HW + pb + ty) * NC + tx] = tile[tx][ty];
}

__device__ __forceinline__ float warp_bfly_sum(float x) {
    const unsigned FULL = 0xffffffffu;
#pragma unroll
    for (int o = 16; o; o >>= 1) x = __fadd_rn(x, __shfl_xor_sync(FULL, x, o));
    return x;
}

// ---------------------------------------------------------------------------
// Main kernel: one warp per ref pixel, lane = depth hypothesis.
// Warp-uniform tap fast path: when all 32 depth lanes share the same integer
// taps (the common case — px spread across depths is ~0.09px), the warp loads
// the 32 (tap,group) float4s cooperatively (1 LDG.128/view), computes each
// dot d=q·rf once, and redistributes through smem. cf bits identical to the
// per-lane slow path (same values, same fma order).
// ---------------------------------------------------------------------------
__global__ void __launch_bounds__(128, 5) stagenet_main(
    const float* __restrict__ depth_hypo,
    const float* __restrict__ reg_w,
    float* __restrict__ out) {
    const unsigned FULL = 0xffffffffu;
    __shared__ float4 rf_s[4][8];
    __shared__ float  d_s[4][32];

    int warp = blockIdx.x * (blockDim.x >> 5) + (threadIdx.x >> 5);
    int wslot = threadIdx.x >> 5;
    int lane = threadIdx.x & 31;

    int b  = warp >> 14;
    int hw = warp & (HW - 1);
    int h  = hw >> 7;
    int w  = hw & (NW - 1);

    const float4* refp = g_featT + ((unsigned)b * HW + hw) * 8;   // view 0
    float4 rf[8];
#pragma unroll
    for (int j = 0; j < 8; j++) rf[j] = __ldg(refp + j);
    if (lane < 8) rf_s[wslot][lane] = rf[lane];
    __syncwarp();

    float dep = depth_hypo[(unsigned)(b * ND + lane) * HW + hw];
    float xw = (float)w, yh = (float)h;

    float acc[8];
#pragma unroll
    for (int j = 0; j < 8; j++) acc[j] = 0.f;
    float cw_sum = 1e-8f;

#pragma unroll
    for (int v = 1; v < NV; v++) {
        const float* R = g_rot[b][v];
        const float* T = g_trans[b][v];
        float rx = fmaf(R[2], 1.f, fmaf(R[1], yh, __fmul_rn(R[0], xw)));
        float ry = fmaf(R[5], 1.f, fmaf(R[4], yh, __fmul_rn(R[3], xw)));
        float rz = fmaf(R[8], 1.f, fmaf(R[7], yh, __fmul_rn(R[6], xw)));
        float X = __fadd_rn(__fmul_rn(rx, dep), T[0]);
        float Y = __fadd_rn(__fmul_rn(ry, dep), T[1]);
        float Z = __fadd_rn(__fmul_rn(rz, dep), T[2]);
        if (Z == 0.f) Z = 1e-9f;
        float px = __fdiv_rn(X, Z);
        float py = __fdiv_rn(Y, Z);

        float x0f = floorf(px), y0f = floorf(py);
        int   x0 = (int)x0f,   y0 = (int)y0f;
        float wx1 = __fsub_rn(px, x0f), wx0 = __fsub_rn(1.f, wx1);
        float wy1 = __fsub_rn(py, y0f), wy0 = __fsub_rn(1.f, wy1);

        int x0c = min(max(x0, 0), NW - 1), x1c = min(max(x0 + 1, 0), NW - 1);
        int y0c = min(max(y0, 0), NH - 1), y1c = min(max(y0 + 1, 0), NH - 1);
        bool vx0 = (x0 >= 0) & (x0 < NW),     vx1 = (x0 + 1 >= 0) & (x0 + 1 < NW);
        bool vy0 = (y0 >= 0) & (y0 < NH),     vy1 = (y0 + 1 >= 0) & (y0 + 1 < NH);
        float wts[4] = {
            (vx0 & vy0) ? __fmul_rn(wx0, wy0) : 0.f,
            (vx1 & vy0) ? __fmul_rn(wx1, wy0) : 0.f,
            (vx0 & vy1) ? __fmul_rn(wx0, wy1) : 0.f,
            (vx1 & vy1) ? __fmul_rn(wx1, wy1) : 0.f };
        const float4* base = g_featT + (unsigned)(v * NB + b) * (HW * 8u);

        bool uni = __all_sync(FULL, x0 == __shfl_sync(FULL, x0, 0)) &&
                   __all_sync(FULL, y0 == __shfl_sync(FULL, y0, 0));

        float cf[8];
        float s;
        if (uni) {
            // Cooperative: lane l handles (tap = l>>3, group = l&7).
            int gl = lane & 7;
            int xc = (lane & 8)  ? x1c : x0c;
            int yc = (lane & 16) ? y1c : y0c;
            unsigned myoff = (unsigned)(yc * NW + xc) * 8u + (unsigned)gl;
            float4 q  = __ldg(base + myoff);
            float4 rq = rf_s[wslot][gl];
            float d = fmaf(q.x, rq.x,
                      fmaf(q.y, rq.y,
                      fmaf(q.z, rq.z, __fmul_rn(q.w, rq.w))));
            d_s[wslot][lane] = d;
            __syncwarp();
            float4 dv[8];
            const float4* dp = (const float4*)d_s[wslot];
#pragma unroll
            for (int i = 0; i < 8; i++) dv[i] = dp[i];
            __syncwarp();

            float pg[8];
#pragma unroll
            for (int g = 0; g < 8; g++) pg[g] = 0.f;
#pragma unroll
            for (int t = 0; t < 4; t++) {
                float wt = wts[t];
#pragma unroll
                for (int g = 0; g < 8; g++) {
                    int idx = t * 8 + g;
                    float4 dq = dv[idx >> 2];
                    float dval = (idx & 3) == 0 ? dq.x :
                                 (idx & 3) == 1 ? dq.y :
                                 (idx & 3) == 2 ? dq.z : dq.w;
                    pg[g] = fmaf(wt, dval, pg[g]);
                }
            }
            s = 0.f;
#pragma unroll
            for (int g = 0; g < 8; g++) {
                cf[g] = __fmul_rn(pg[g], 0.25f);
                s = (g == 0) ? cf[0] : __fadd_rn(s, cf[g]);
            }
        } else {
            unsigned off[4] = {
                (unsigned)(y0c * NW + x0c) * 8u,
                (unsigned)(y0c * NW + x1c) * 8u,
                (unsigned)(y1c * NW + x0c) * 8u,
                (unsigned)(y1c * NW + x1c) * 8u };
            float pg[8];
#pragma unroll
            for (int g = 0; g < 8; g++) pg[g] = 0.f;
#pragma unroll
            for (int t = 0; t < 4; t++) {
                float wt = wts[t];
                const float4* tp = base + off[t];
#pragma unroll
                for (int g = 0; g < 8; g++) {
                    float4 q = __ldg(tp + g);
                    float d = fmaf(q.x, rf[g].x,
                              fmaf(q.y, rf[g].y,
                              fmaf(q.z, rf[g].z, __fmul_rn(q.w, rf[g].w))));
                    pg[g] = fmaf(wt, d, pg[g]);
                }
            }
            s = 0.f;
#pragma unroll
            for (int g = 0; g < 8; g++) {
                cf[g] = __fmul_rn(pg[g], 0.25f);
                s = (g == 0) ? cf[0] : __fadd_rn(s, cf[g]);
            }
        }

        // softmax over depth lanes
        float m = s;
#pragma unroll
        for (int o = 16; o; o >>= 1) m = fmaxf(m, __shfl_xor_sync(FULL, m, o));
        float e = expf(__fsub_rn(s, m));
        float es = warp_bfly_sum(e);
        float wv = __fmul_rn(__fdiv_rn(e, es), 0.17677669529663687f);  // 1/sqrt(32)

        cw_sum = __fadd_rn(cw_sum, wv);
#pragma unroll
        for (int g = 0; g < 8; g++)
            acc[g] = fmaf(wv, cf[g], acc[g]);
    }

    // cor_feats / cor_weight_sum, then reg_w contraction (fma chain)
    float logit = 0.f;
#pragma unroll
    for (int g = 0; g < 8; g++) {
        float vgl = __fdiv_rn(acc[g], cw_sum);
        float rw  = __ldg(reg_w + g);
        logit = (g == 0) ? __fmul_rn(rw, vgl) : fmaf(rw, vgl, logit);
    }

    // final softmax over depth
    float m2 = logit;
#pragma unroll
    for (int o = 16; o; o >>= 1) m2 = fmaxf(m2, __shfl_xor_sync(FULL, m2, o));
    float e2 = expf(__fsub_rn(logit, m2));
    float es2 = warp_bfly_sum(e2);
    float attn = __fdiv_rn(e2, es2);

    // outputs: [depth (B*H*W)] then [attn (B*D*H*W)]
    out[(unsigned)NB * HW + (unsigned)(b * ND + lane) * HW + hw] = attn;

    float amax = attn;
#pragma unroll
    for (int o = 16; o; o >>= 1) amax = fmaxf(amax, __shfl_xor_sync(FULL, amax, o));
    unsigned msk = __ballot_sync(FULL, attn == amax);
    int idx = __ffs(msk) - 1;   // first max, matching jnp.argmax
    if (lane == idx) out[(unsigned)b * HW + hw] = dep;
}

// ---------------------------------------------------------------------------
// Launch
// ---------------------------------------------------------------------------
extern "C" void kernel_launch(void* const* d_in, const int* in_sizes, int n_in,
                              void* d_out, int out_size) {
    const float* features   = (const float*)d_in[0];
    const float* proj       = (const float*)d_in[1];
    const float* depth_hypo = (const float*)d_in[2];
    const float* reg_w      = (const float*)d_in[3];
    float* out = (float*)d_out;

    prep_kernel<<<dim3(HW / 32, NV * NB), dim3(32, 32)>>>(features, proj);
    stagenet_main<<<(NB * HW) / 4, 128>>>(depth_hypo, reg_w, out);
}

// round 10
// speedup vs baseline: 1.8964x; 1.2841x over previous
#include <cuda_runtime.h>
#include <cstdint>

// Problem constants (stagenet_46445776339346): V=5, B=2, C=32, H=W=128, D=32, G=8
#define NV 5
#define NB 2
#define NC 32
#define NH 128
#define NW 128
#define ND 32
#define NG 8
#define HW (NH * NW)

// ---------------------------------------------------------------------------
// Device scratch (no runtime allocation allowed)
// ---------------------------------------------------------------------------
__device__ float  g_rot[NB][NV][9];
__device__ float  g_trans[NB][NV][3];
// features transposed to [V, B, H*W, C]: one bilinear tap = 128 contiguous bytes.
__device__ float4 g_featT[(size_t)NV * NB * HW * (NC / 4)];

// ---------------------------------------------------------------------------
// FROZEN NUMERICS: fp32 4x4 inverse = sgetf2 LU + OpenBLAS-style trsm
// (pre-inverted diagonal). Do not touch.
// ---------------------------------------------------------------------------
__device__ void inv4_lapack_f32(const float* A_rm, float* Ai_rm) {
    float a[16];
    int   piv[4];
#pragma unroll
    for (int r = 0; r < 4; r++)
#pragma unroll
        for (int c = 0; c < 4; c++) a[c * 4 + r] = A_rm[r * 4 + c];

#pragma unroll
    for (int j = 0; j < 4; j++) {
        int jp = j; float amax = fabsf(a[j * 4 + j]);
        for (int i = j + 1; i < 4; i++) {
            float v = fabsf(a[j * 4 + i]);
            if (v > amax) { amax = v; jp = i; }
        }
        piv[j] = jp;
        if (jp != j)
#pragma unroll
            for (int c = 0; c < 4; c++) {
                float t = a[c * 4 + j]; a[c * 4 + j] = a[c * 4 + jp]; a[c * 4 + jp] = t;
            }
        float ainv = __fdiv_rn(1.0f, a[j * 4 + j]);
        for (int i = j + 1; i < 4; i++)
            a[j * 4 + i] = __fmul_rn(a[j * 4 + i], ainv);
        for (int k = j + 1; k < 4; k++) {
            float temp = -a[k * 4 + j];
            for (int i = j + 1; i < 4; i++)
                a[k * 4 + i] = fmaf(a[j * 4 + i], temp, a[k * 4 + i]);
        }
    }

    float dinv[4];
#pragma unroll
    for (int k = 0; k < 4; k++) dinv[k] = __fdiv_rn(1.0f, a[k * 4 + k]);

#pragma unroll
    for (int c = 0; c < 4; c++) {
        float b[4] = {0.f, 0.f, 0.f, 0.f};
        b[c] = 1.0f;
#pragma unroll
        for (int j = 0; j < 4; j++) { float t = b[j]; b[j] = b[piv[j]]; b[piv[j]] = t; }
#pragma unroll
        for (int k = 0; k < 4; k++) {
            float bk = b[k];
            if (bk != 0.f)
                for (int i = k + 1; i < 4; i++)
                    b[i] = fmaf(-bk, a[k * 4 + i], b[i]);
        }
#pragma unroll
        for (int k = 3; k >= 0; k--) {
            b[k] = __fmul_rn(b[k], dinv[k]);
            float bk = b[k];
            for (int i = 0; i < k; i++)
                b[i] = fmaf(-bk, a[k * 4 + i], b[i]);
        }
#pragma unroll
        for (int r = 0; r < 4; r++) Ai_rm[r * 4 + c] = b[r];
    }
}

__device__ void make_comb_f32(const float* pm, int b, int v, float* M) {
    const float* ext = pm + ((size_t)(b * NV + v) * 2 + 0) * 16;
    const float* K   = pm + ((size_t)(b * NV + v) * 2 + 1) * 16;
#pragma unroll
    for (int r = 0; r < 3; r++)
#pragma unroll
        for (int c = 0; c < 4; c++) {
            float s = __fmul_rn(K[r * 4 + 0], ext[0 * 4 + c]);
            s = fmaf(K[r * 4 + 1], ext[1 * 4 + c], s);
            s = fmaf(K[r * 4 + 2], ext[2 * 4 + c], s);
            M[r * 4 + c] = s;
        }
#pragma unroll
    for (int c = 0; c < 4; c++) M[12 + c] = ext[12 + c];
}

__device__ void do_setup(const float* pm, int b) {
    float Mr[16], Mi[16];
    make_comb_f32(pm, b, 0, Mr);
    inv4_lapack_f32(Mr, Mi);
    for (int v = 1; v < NV; v++) {
        float Ms[16];
        make_comb_f32(pm, b, v, Ms);
        for (int r = 0; r < 3; r++) {
            for (int c = 0; c < 4; c++) {
                float s = __fmul_rn(Ms[r * 4 + 0], Mi[0 * 4 + c]);
                s = fmaf(Ms[r * 4 + 1], Mi[1 * 4 + c], s);
                s = fmaf(Ms[r * 4 + 2], Mi[2 * 4 + c], s);
                s = fmaf(Ms[r * 4 + 3], Mi[3 * 4 + c], s);
                if (c < 3) g_rot[b][v][r * 3 + c] = s;
                else       g_trans[b][v][r] = s;
            }
        }
    }
}

// ---------------------------------------------------------------------------
// Prep kernel: feature transpose + projection setup (overlapped).
// ---------------------------------------------------------------------------
__global__ void prep_kernel(const float* __restrict__ fea,
                            const float* __restrict__ pm) {
    __shared__ float tile[32][33];
    int vb = blockIdx.y;
    int pb = blockIdx.x * 32;
    int tx = threadIdx.x, ty = threadIdx.y;

    if (blockIdx.x == 0 && blockIdx.y == 0 && ty == 1 && tx < NB)
        do_setup(pm, tx);

    tile[ty][tx] = fea[(size_t)vb * NC * HW + (size_t)ty * HW + pb + tx];
    __syncthreads();
    ((float*)g_featT)[((size_t)vb * HW + pb + ty) * NC + tx] = tile[tx][ty];
}

__device__ __forceinline__ float warp_bfly_sum(float x) {
    const unsigned FULL = 0xffffffffu;
#pragma unroll
    for (int o = 16; o; o >>= 1) x = __fadd_rn(x, __shfl_xor_sync(FULL, x, o));
    return x;
}

// ---------------------------------------------------------------------------
// Main kernel: one warp per ref pixel, lane = depth hypothesis.
// rf and per-view tap dots live in smem (broadcast LDS) — registers spent on
// occupancy instead: 64-reg budget, 8 blocks/SM = 32 warps (50% occ).
// ---------------------------------------------------------------------------
__global__ void __launch_bounds__(128, 8) stagenet_main(
    const float* __restrict__ depth_hypo,
    const float* __restrict__ reg_w,
    float* __restrict__ out) {
    const unsigned FULL = 0xffffffffu;
    __shared__ float4 rf_s[4][8];
    __shared__ float  d_s[4][32];

    int warp = blockIdx.x * (blockDim.x >> 5) + (threadIdx.x >> 5);
    int wslot = threadIdx.x >> 5;
    int lane = threadIdx.x & 31;

    int b  = warp >> 14;
    int hw = warp & (HW - 1);
    int h  = hw >> 7;
    int w  = hw & (NW - 1);

    // Load ref feature cooperatively into smem (8 lanes, one float4 each).
    if (lane < 8)
        rf_s[wslot][lane] = __ldg(g_featT + ((unsigned)b * HW + hw) * 8 + lane);
    __syncwarp();

    float dep = depth_hypo[(unsigned)(b * ND + lane) * HW + hw];
    float xw = (float)w, yh = (float)h;

    float acc[8];
#pragma unroll
    for (int j = 0; j < 8; j++) acc[j] = 0.f;
    float cw_sum = 1e-8f;

#pragma unroll
    for (int v = 1; v < NV; v++) {
        const float* R = g_rot[b][v];
        const float* T = g_trans[b][v];
        float rx = fmaf(R[2], 1.f, fmaf(R[1], yh, __fmul_rn(R[0], xw)));
        float ry = fmaf(R[5], 1.f, fmaf(R[4], yh, __fmul_rn(R[3], xw)));
        float rz = fmaf(R[8], 1.f, fmaf(R[7], yh, __fmul_rn(R[6], xw)));
        float X = __fadd_rn(__fmul_rn(rx, dep), T[0]);
        float Y = __fadd_rn(__fmul_rn(ry, dep), T[1]);
        float Z = __fadd_rn(__fmul_rn(rz, dep), T[2]);
        if (Z == 0.f) Z = 1e-9f;
        float px = __fdiv_rn(X, Z);
        float py = __fdiv_rn(Y, Z);

        float x0f = floorf(px), y0f = floorf(py);
        int   x0 = (int)x0f,   y0 = (int)y0f;
        float wx1 = __fsub_rn(px, x0f), wx0 = __fsub_rn(1.f, wx1);
        float wy1 = __fsub_rn(py, y0f), wy0 = __fsub_rn(1.f, wy1);

        int x0c = min(max(x0, 0), NW - 1), x1c = min(max(x0 + 1, 0), NW - 1);
        int y0c = min(max(y0, 0), NH - 1), y1c = min(max(y0 + 1, 0), NH - 1);
        bool vx0 = (x0 >= 0) & (x0 < NW),     vx1 = (x0 + 1 >= 0) & (x0 + 1 < NW);
        bool vy0 = (y0 >= 0) & (y0 < NH),     vy1 = (y0 + 1 >= 0) & (y0 + 1 < NH);
        float wts[4] = {
            (vx0 & vy0) ? __fmul_rn(wx0, wy0) : 0.f,
            (vx1 & vy0) ? __fmul_rn(wx1, wy0) : 0.f,
            (vx0 & vy1) ? __fmul_rn(wx0, wy1) : 0.f,
            (vx1 & vy1) ? __fmul_rn(wx1, wy1) : 0.f };
        const float4* base = g_featT + (unsigned)(v * NB + b) * (HW * 8u);

        bool uni = __all_sync(FULL, x0 == __shfl_sync(FULL, x0, 0)) &&
                   __all_sync(FULL, y0 == __shfl_sync(FULL, y0, 0));

        float pg[8];
#pragma unroll
        for (int g = 0; g < 8; g++) pg[g] = 0.f;

        if (uni) {
            // Cooperative: lane l handles (tap = l>>3, group = l&7).
            int gl = lane & 7;
            int xc = (lane & 8)  ? x1c : x0c;
            int yc = (lane & 16) ? y1c : y0c;
            float4 q  = __ldg(base + (unsigned)(yc * NW + xc) * 8u + (unsigned)gl);
            float4 rq = rf_s[wslot][gl];
            float d = fmaf(q.x, rq.x,
                      fmaf(q.y, rq.y,
                      fmaf(q.z, rq.z, __fmul_rn(q.w, rq.w))));
            d_s[wslot][lane] = d;
            __syncwarp();
            const float4* dp = (const float4*)d_s[wslot];
#pragma unroll
            for (int t = 0; t < 4; t++) {
                float wt = wts[t];
                float4 d0 = dp[t * 2 + 0];   // d[t*8 + 0..3]
                float4 d1 = dp[t * 2 + 1];   // d[t*8 + 4..7]
                pg[0] = fmaf(wt, d0.x, pg[0]);
                pg[1] = fmaf(wt, d0.y, pg[1]);
                pg[2] = fmaf(wt, d0.z, pg[2]);
                pg[3] = fmaf(wt, d0.w, pg[3]);
                pg[4] = fmaf(wt, d1.x, pg[4]);
                pg[5] = fmaf(wt, d1.y, pg[5]);
                pg[6] = fmaf(wt, d1.z, pg[6]);
                pg[7] = fmaf(wt, d1.w, pg[7]);
            }
            __syncwarp();
        } else {
            unsigned off[4] = {
                (unsigned)(y0c * NW + x0c) * 8u,
                (unsigned)(y0c * NW + x1c) * 8u,
                (unsigned)(y1c * NW + x0c) * 8u,
                (unsigned)(y1c * NW + x1c) * 8u };
#pragma unroll
            for (int t = 0; t < 4; t++) {
                float wt = wts[t];
                const float4* tp = base + off[t];
#pragma unroll
                for (int g = 0; g < 8; g++) {
                    float4 q  = __ldg(tp + g);
                    float4 rq = rf_s[wslot][g];
                    float d = fmaf(q.x, rq.x,
                              fmaf(q.y, rq.y,
                              fmaf(q.z, rq.z, __fmul_rn(q.w, rq.w))));
                    pg[g] = fmaf(wt, d, pg[g]);
                }
            }
        }

        float cf[8];
        float s = 0.f;
#pragma unroll
        for (int g = 0; g < 8; g++) {
            cf[g] = __fmul_rn(pg[g], 0.25f);
            s = (g == 0) ? cf[0] : __fadd_rn(s, cf[g]);
        }

        // softmax over depth lanes
        float m = s;
#pragma unroll
        for (int o = 16; o; o >>= 1) m = fmaxf(m, __shfl_xor_sync(FULL, m, o));
        float e = expf(__fsub_rn(s, m));
        float es = warp_bfly_sum(e);
        float wv = __fmul_rn(__fdiv_rn(e, es), 0.17677669529663687f);  // 1/sqrt(32)

        cw_sum = __fadd_rn(cw_sum, wv);
#pragma unroll
        for (int g = 0; g < 8; g++)
            acc[g] = fmaf(wv, cf[g], acc[g]);
    }

    // cor_feats / cor_weight_sum, then reg_w contraction (fma chain)
    float logit = 0.f;
#pragma unroll
    for (int g = 0; g < 8; g++) {
        float vgl = __fdiv_rn(acc[g], cw_sum);
        float rw  = __ldg(reg_w + g);
        logit = (g == 0) ? __fmul_rn(rw, vgl) : fmaf(rw, vgl, logit);
    }

    // final softmax over depth
    float m2 = logit;
#pragma unroll
    for (int o = 16; o; o >>= 1) m2 = fmaxf(m2, __shfl_xor_sync(FULL, m2, o));
    float e2 = expf(__fsub_rn(logit, m2));
    float es2 = warp_bfly_sum(e2);
    float attn = __fdiv_rn(e2, es2);

    // outputs: [depth (B*H*W)] then [attn (B*D*H*W)]
    out[(unsigned)NB * HW + (unsigned)(b * ND + lane) * HW + hw] = attn;

    float amax = attn;
#pragma unroll
    for (int o = 16; o; o >>= 1) amax = fmaxf(amax, __shfl_xor_sync(FULL, amax, o));
    unsigned msk = __ballot_sync(FULL, attn == amax);
    int idx = __ffs(msk) - 1;   // first max, matching jnp.argmax
    if (lane == idx) out[(unsigned)b * HW + hw] = dep;
}

// ---------------------------------------------------------------------------
// Launch
// ---------------------------------------------------------------------------
extern "C" void kernel_launch(void* const* d_in, const int* in_sizes, int n_in,
                              void* d_out, int out_size) {
    const float* features   = (const float*)d_in[0];
    const float* proj       = (const float*)d_in[1];
    const float* depth_hypo = (const float*)d_in[2];
    const float* reg_w      = (const float*)d_in[3];
    float* out = (float*)d_out;

    prep_kernel<<<dim3(HW / 32, NV * NB), dim3(32, 32)>>>(features, proj);
    stagenet_main<<<(NB * HW) / 4, 128>>>(depth_hypo, reg_w, out);
}

// round 11
// speedup vs baseline: 2.0504x; 1.0812x over previous
#include <cuda_runtime.h>
#include <cstdint>

// Problem constants (stagenet_46445776339346): V=5, B=2, C=32, H=W=128, D=32, G=8
#define NV 5
#define NB 2
#define NC 32
#define NH 128
#define NW 128
#define ND 32
#define NG 8
#define HW (NH * NW)

// ---------------------------------------------------------------------------
// Device scratch (no runtime allocation allowed)
// ---------------------------------------------------------------------------
__device__ float  g_rot[NB][NV][9];
__device__ float  g_trans[NB][NV][3];
// features transposed to [V, B, H*W, C]: one bilinear tap = 128 contiguous bytes.
__device__ float4 g_featT[(size_t)NV * NB * HW * (NC / 4)];

// ---------------------------------------------------------------------------
// FROZEN NUMERICS: fp32 4x4 inverse = sgetf2 LU + OpenBLAS-style trsm
// (pre-inverted diagonal). Do not touch.
// ---------------------------------------------------------------------------
__device__ void inv4_lapack_f32(const float* A_rm, float* Ai_rm) {
    float a[16];
    int   piv[4];
#pragma unroll
    for (int r = 0; r < 4; r++)
#pragma unroll
        for (int c = 0; c < 4; c++) a[c * 4 + r] = A_rm[r * 4 + c];

#pragma unroll
    for (int j = 0; j < 4; j++) {
        int jp = j; float amax = fabsf(a[j * 4 + j]);
        for (int i = j + 1; i < 4; i++) {
            float v = fabsf(a[j * 4 + i]);
            if (v > amax) { amax = v; jp = i; }
        }
        piv[j] = jp;
        if (jp != j)
#pragma unroll
            for (int c = 0; c < 4; c++) {
                float t = a[c * 4 + j]; a[c * 4 + j] = a[c * 4 + jp]; a[c * 4 + jp] = t;
            }
        float ainv = __fdiv_rn(1.0f, a[j * 4 + j]);
        for (int i = j + 1; i < 4; i++)
            a[j * 4 + i] = __fmul_rn(a[j * 4 + i], ainv);
        for (int k = j + 1; k < 4; k++) {
            float temp = -a[k * 4 + j];
            for (int i = j + 1; i < 4; i++)
                a[k * 4 + i] = fmaf(a[j * 4 + i], temp, a[k * 4 + i]);
        }
    }

    float dinv[4];
#pragma unroll
    for (int k = 0; k < 4; k++) dinv[k] = __fdiv_rn(1.0f, a[k * 4 + k]);

#pragma unroll
    for (int c = 0; c < 4; c++) {
        float b[4] = {0.f, 0.f, 0.f, 0.f};
        b[c] = 1.0f;
#pragma unroll
        for (int j = 0; j < 4; j++) { float t = b[j]; b[j] = b[piv[j]]; b[piv[j]] = t; }
#pragma unroll
        for (int k = 0; k < 4; k++) {
            float bk = b[k];
            if (bk != 0.f)
                for (int i = k + 1; i < 4; i++)
                    b[i] = fmaf(-bk, a[k * 4 + i], b[i]);
        }
#pragma unroll
        for (int k = 3; k >= 0; k--) {
            b[k] = __fmul_rn(b[k], dinv[k]);
            float bk = b[k];
            for (int i = 0; i < k; i++)
                b[i] = fmaf(-bk, a[k * 4 + i], b[i]);
        }
#pragma unroll
        for (int r = 0; r < 4; r++) Ai_rm[r * 4 + c] = b[r];
    }
}

__device__ void make_comb_f32(const float* pm, int b, int v, float* M) {
    const float* ext = pm + ((size_t)(b * NV + v) * 2 + 0) * 16;
    const float* K   = pm + ((size_t)(b * NV + v) * 2 + 1) * 16;
#pragma unroll
    for (int r = 0; r < 3; r++)
#pragma unroll
        for (int c = 0; c < 4; c++) {
            float s = __fmul_rn(K[r * 4 + 0], ext[0 * 4 + c]);
            s = fmaf(K[r * 4 + 1], ext[1 * 4 + c], s);
            s = fmaf(K[r * 4 + 2], ext[2 * 4 + c], s);
            M[r * 4 + c] = s;
        }
#pragma unroll
    for (int c = 0; c < 4; c++) M[12 + c] = ext[12 + c];
}

__device__ void do_setup(const float* pm, int b) {
    float Mr[16], Mi[16];
    make_comb_f32(pm, b, 0, Mr);
    inv4_lapack_f32(Mr, Mi);
    for (int v = 1; v < NV; v++) {
        float Ms[16];
        make_comb_f32(pm, b, v, Ms);
        for (int r = 0; r < 3; r++) {
            for (int c = 0; c < 4; c++) {
                float s = __fmul_rn(Ms[r * 4 + 0], Mi[0 * 4 + c]);
                s = fmaf(Ms[r * 4 + 1], Mi[1 * 4 + c], s);
                s = fmaf(Ms[r * 4 + 2], Mi[2 * 4 + c], s);
                s = fmaf(Ms[r * 4 + 3], Mi[3 * 4 + c], s);
                if (c < 3) g_rot[b][v][r * 3 + c] = s;
                else       g_trans[b][v][r] = s;
            }
        }
    }
}

// ---------------------------------------------------------------------------
// Prep kernel: feature transpose + projection setup (overlapped).
// ---------------------------------------------------------------------------
__global__ void prep_kernel(const float* __restrict__ fea,
                            const float* __restrict__ pm) {
    __shared__ float tile[32][33];
    int vb = blockIdx.y;
    int pb = blockIdx.x * 32;
    int tx = threadIdx.x, ty = threadIdx.y;

    if (blockIdx.x == 0 && blockIdx.y == 0 && ty == 1 && tx < NB)
        do_setup(pm, tx);

    tile[ty][tx] = fea[(size_t)vb * NC * HW + (size_t)ty * HW + pb + tx];
    __syncthreads();
    ((float*)g_featT)[((size_t)vb * HW + pb + ty) * NC + tx] = tile[tx][ty];
}

__device__ __forceinline__ float warp_bfly_sum(float x) {
    const unsigned FULL = 0xffffffffu;
#pragma unroll
    for (int o = 16; o; o >>= 1) x = __fadd_rn(x, __shfl_xor_sync(FULL, x, o));
    return x;
}

// Butterfly sum within each 8-lane group (offsets 1,2,4).
__device__ __forceinline__ float group8_sum(float x) {
    const unsigned FULL = 0xffffffffu;
#pragma unroll
    for (int o = 1; o < 8; o <<= 1) x = __fadd_rn(x, __shfl_xor_sync(FULL, x, o));
    return x;
}

// ---------------------------------------------------------------------------
// Main kernel: one warp per ref pixel, lane = depth hypothesis.
// Per-view state collapsed to two scalars (s = sum_g cf, r = sum_g rw*cf):
// fast path computes them via 8-lane butterflies over the warp-shared tap
// dots — no smem traffic, no per-lane register arrays.
// ---------------------------------------------------------------------------
__global__ void __launch_bounds__(128, 10) stagenet_main(
    const float* __restrict__ depth_hypo,
    const float* __restrict__ reg_w,
    float* __restrict__ out) {
    const unsigned FULL = 0xffffffffu;
    __shared__ float4 rf_s[4][8];

    int warp = blockIdx.x * (blockDim.x >> 5) + (threadIdx.x >> 5);
    int wslot = threadIdx.x >> 5;
    int lane = threadIdx.x & 31;
    int gl   = lane & 7;

    int b  = warp >> 14;
    int hw = warp & (HW - 1);
    int h  = hw >> 7;
    int w  = hw & (NW - 1);

    // Ref feature into smem, then each lane keeps its group's float4.
    if (lane < 8)
        rf_s[wslot][lane] = __ldg(g_featT + ((unsigned)b * HW + hw) * 8 + lane);
    __syncwarp();
    float4 rfl = rf_s[wslot][gl];
    float  rw_l = __ldg(reg_w + gl);

    float dep = depth_hypo[(unsigned)(b * ND + lane) * HW + hw];
    float xw = (float)w, yh = (float)h;

    float acc_r = 0.f;
    float cw_sum = 1e-8f;

#pragma unroll
    for (int v = 1; v < NV; v++) {
        const float* R = g_rot[b][v];
        const float* T = g_trans[b][v];
        float rx = fmaf(R[2], 1.f, fmaf(R[1], yh, __fmul_rn(R[0], xw)));
        float ry = fmaf(R[5], 1.f, fmaf(R[4], yh, __fmul_rn(R[3], xw)));
        float rz = fmaf(R[8], 1.f, fmaf(R[7], yh, __fmul_rn(R[6], xw)));
        float X = __fadd_rn(__fmul_rn(rx, dep), T[0]);
        float Y = __fadd_rn(__fmul_rn(ry, dep), T[1]);
        float Z = __fadd_rn(__fmul_rn(rz, dep), T[2]);
        if (Z == 0.f) Z = 1e-9f;
        float px = __fdiv_rn(X, Z);
        float py = __fdiv_rn(Y, Z);

        float x0f = floorf(px), y0f = floorf(py);
        int   x0 = (int)x0f,   y0 = (int)y0f;
        float wx1 = __fsub_rn(px, x0f), wx0 = __fsub_rn(1.f, wx1);
        float wy1 = __fsub_rn(py, y0f), wy0 = __fsub_rn(1.f, wy1);

        int x0c = min(max(x0, 0), NW - 1), x1c = min(max(x0 + 1, 0), NW - 1);
        int y0c = min(max(y0, 0), NH - 1), y1c = min(max(y0 + 1, 0), NH - 1);
        bool vx0 = (x0 >= 0) & (x0 < NW),     vx1 = (x0 + 1 >= 0) & (x0 + 1 < NW);
        bool vy0 = (y0 >= 0) & (y0 < NH),     vy1 = (y0 + 1 >= 0) & (y0 + 1 < NH);
        float wts[4] = {
            (vx0 & vy0) ? __fmul_rn(wx0, wy0) : 0.f,
            (vx1 & vy0) ? __fmul_rn(wx1, wy0) : 0.f,
            (vx0 & vy1) ? __fmul_rn(wx0, wy1) : 0.f,
            (vx1 & vy1) ? __fmul_rn(wx1, wy1) : 0.f };
        const float4* base = g_featT + (unsigned)(v * NB + b) * (HW * 8u);

        bool uni = __all_sync(FULL, x0 == __shfl_sync(FULL, x0, 0)) &&
                   __all_sync(FULL, y0 == __shfl_sync(FULL, y0, 0));

        float s, r;
        if (uni) {
            // lane l handles (tap = l>>3, group = l&7); taps warp-uniform.
            int xc = (lane & 8)  ? x1c : x0c;
            int yc = (lane & 16) ? y1c : y0c;
            float4 q = __ldg(base + (unsigned)(yc * NW + xc) * 8u + (unsigned)gl);
            float d = fmaf(q.x, rfl.x,
                      fmaf(q.y, rfl.y,
                      fmaf(q.z, rfl.z, __fmul_rn(q.w, rfl.w))));
            float D  = group8_sum(d);                       // sum_g d[t,g]
            float Dr = group8_sum(__fmul_rn(rw_l, d));      // sum_g rw_g*d[t,g]
            // gather the 4 tap sums (uniform within each 8-lane group)
            float D0  = __shfl_sync(FULL, D, 0),  D1  = __shfl_sync(FULL, D, 8);
            float D2  = __shfl_sync(FULL, D, 16), D3  = __shfl_sync(FULL, D, 24);
            float Dr0 = __shfl_sync(FULL, Dr, 0),  Dr1 = __shfl_sync(FULL, Dr, 8);
            float Dr2 = __shfl_sync(FULL, Dr, 16), Dr3 = __shfl_sync(FULL, Dr, 24);
            s = __fmul_rn(0.25f, fmaf(wts[3], D3, fmaf(wts[2], D2,
                          fmaf(wts[1], D1, __fmul_rn(wts[0], D0)))));
            r = __fmul_rn(0.25f, fmaf(wts[3], Dr3, fmaf(wts[2], Dr2,
                          fmaf(wts[1], Dr1, __fmul_rn(wts[0], Dr0)))));
        } else {
            unsigned off[4] = {
                (unsigned)(y0c * NW + x0c) * 8u,
                (unsigned)(y0c * NW + x1c) * 8u,
                (unsigned)(y1c * NW + x0c) * 8u,
                (unsigned)(y1c * NW + x1c) * 8u };
            float pg[8];
#pragma unroll
            for (int g = 0; g < 8; g++) pg[g] = 0.f;
#pragma unroll
            for (int t = 0; t < 4; t++) {
                float wt = wts[t];
                const float4* tp = base + off[t];
#pragma unroll
                for (int g = 0; g < 8; g++) {
                    float4 q  = __ldg(tp + g);
                    float4 rq = rf_s[wslot][g];
                    float d = fmaf(q.x, rq.x,
                              fmaf(q.y, rq.y,
                              fmaf(q.z, rq.z, __fmul_rn(q.w, rq.w))));
                    pg[g] = fmaf(wt, d, pg[g]);
                }
            }
            s = 0.f; r = 0.f;
#pragma unroll
            for (int g = 0; g < 8; g++) {
                float cfg = __fmul_rn(pg[g], 0.25f);
                float rwg = __shfl_sync(FULL, rw_l, g);
                s = (g == 0) ? cfg : __fadd_rn(s, cfg);
                r = (g == 0) ? __fmul_rn(rwg, cfg) : fmaf(rwg, cfg, r);
            }
        }

        // softmax over depth lanes
        float m = s;
#pragma unroll
        for (int o = 16; o; o >>= 1) m = fmaxf(m, __shfl_xor_sync(FULL, m, o));
        float e = expf(__fsub_rn(s, m));
        float es = warp_bfly_sum(e);
        float wv = __fmul_rn(__fdiv_rn(e, es), 0.17677669529663687f);  // 1/sqrt(32)

        cw_sum = __fadd_rn(cw_sum, wv);
        acc_r  = fmaf(wv, r, acc_r);
    }

    float logit = __fdiv_rn(acc_r, cw_sum);

    // final softmax over depth
    float m2 = logit;
#pragma unroll
    for (int o = 16; o; o >>= 1) m2 = fmaxf(m2, __shfl_xor_sync(FULL, m2, o));
    float e2 = expf(__fsub_rn(logit, m2));
    float es2 = warp_bfly_sum(e2);
    float attn = __fdiv_rn(e2, es2);

    // outputs: [depth (B*H*W)] then [attn (B*D*H*W)]
    out[(unsigned)NB * HW + (unsigned)(b * ND + lane) * HW + hw] = attn;

    float amax = attn;
#pragma unroll
    for (int o = 16; o; o >>= 1) amax = fmaxf(amax, __shfl_xor_sync(FULL, amax, o));
    unsigned msk = __ballot_sync(FULL, attn == amax);
    int idx = __ffs(msk) - 1;   // first max, matching jnp.argmax
    if (lane == idx) out[(unsigned)b * HW + hw] = dep;
}

// ---------------------------------------------------------------------------
// Launch
// ---------------------------------------------------------------------------
extern "C" void kernel_launch(void* const* d_in, const int* in_sizes, int n_in,
                              void* d_out, int out_size) {
    const float* features   = (const float*)d_in[0];
    const float* proj       = (const float*)d_in[1];
    const float* depth_hypo = (const float*)d_in[2];
    const float* reg_w      = (const float*)d_in[3];
    float* out = (float*)d_out;

    prep_kernel<<<dim3(HW / 32, NV * NB), dim3(32, 32)>>>(features, proj);
    stagenet_main<<<(NB * HW) / 4, 128>>>(depth_hypo, reg_w, out);
}

// round 13
// speedup vs baseline: 2.5643x; 1.2506x over previous
#include <cuda_runtime.h>
#include <cstdint>

// Problem constants (stagenet_46445776339346): V=5, B=2, C=32, H=W=128, D=32, G=8
#define NV 5
#define NB 2
#define NC 32
#define NH 128
#define NW 128
#define ND 32
#define NG 8
#define HW (NH * NW)

// ---------------------------------------------------------------------------
// Device scratch (no runtime allocation allowed)
// ---------------------------------------------------------------------------
__device__ float  g_rot[NB][NV][9];
__device__ float  g_trans[NB][NV][3];
// features transposed to [V, B, H*W, C]: one bilinear tap = 128 contiguous bytes.
__device__ float4 g_featT[(size_t)NV * NB * HW * (NC / 4)];

// ---------------------------------------------------------------------------
// FROZEN NUMERICS: fp32 4x4 inverse = sgetf2 LU + OpenBLAS-style trsm
// (pre-inverted diagonal). Do not touch.
// ---------------------------------------------------------------------------
__device__ void inv4_lapack_f32(const float* A_rm, float* Ai_rm) {
    float a[16];
    int   piv[4];
#pragma unroll
    for (int r = 0; r < 4; r++)
#pragma unroll
        for (int c = 0; c < 4; c++) a[c * 4 + r] = A_rm[r * 4 + c];

#pragma unroll
    for (int j = 0; j < 4; j++) {
        int jp = j; float amax = fabsf(a[j * 4 + j]);
        for (int i = j + 1; i < 4; i++) {
            float v = fabsf(a[j * 4 + i]);
            if (v > amax) { amax = v; jp = i; }
        }
        piv[j] = jp;
        if (jp != j)
#pragma unroll
            for (int c = 0; c < 4; c++) {
                float t = a[c * 4 + j]; a[c * 4 + j] = a[c * 4 + jp]; a[c * 4 + jp] = t;
            }
        float ainv = __fdiv_rn(1.0f, a[j * 4 + j]);
        for (int i = j + 1; i < 4; i++)
            a[j * 4 + i] = __fmul_rn(a[j * 4 + i], ainv);
        for (int k = j + 1; k < 4; k++) {
            float temp = -a[k * 4 + j];
            for (int i = j + 1; i < 4; i++)
                a[k * 4 + i] = fmaf(a[j * 4 + i], temp, a[k * 4 + i]);
        }
    }

    float dinv[4];
#pragma unroll
    for (int k = 0; k < 4; k++) dinv[k] = __fdiv_rn(1.0f, a[k * 4 + k]);

#pragma unroll
    for (int c = 0; c < 4; c++) {
        float b[4] = {0.f, 0.f, 0.f, 0.f};
        b[c] = 1.0f;
#pragma unroll
        for (int j = 0; j < 4; j++) { float t = b[j]; b[j] = b[piv[j]]; b[piv[j]] = t; }
#pragma unroll
        for (int k = 0; k < 4; k++) {
            float bk = b[k];
            if (bk != 0.f)
                for (int i = k + 1; i < 4; i++)
                    b[i] = fmaf(-bk, a[k * 4 + i], b[i]);
        }
#pragma unroll
        for (int k = 3; k >= 0; k--) {
            b[k] = __fmul_rn(b[k], dinv[k]);
            float bk = b[k];
            for (int i = 0; i < k; i++)
                b[i] = fmaf(-bk, a[k * 4 + i], b[i]);
        }
#pragma unroll
        for (int r = 0; r < 4; r++) Ai_rm[r * 4 + c] = b[r];
    }
}

__device__ void make_comb_f32(const float* pm, int b, int v, float* M) {
    const float* ext = pm + ((size_t)(b * NV + v) * 2 + 0) * 16;
    const float* K   = pm + ((size_t)(b * NV + v) * 2 + 1) * 16;
#pragma unroll
    for (int r = 0; r < 3; r++)
#pragma unroll
        for (int c = 0; c < 4; c++) {
            float s = __fmul_rn(K[r * 4 + 0], ext[0 * 4 + c]);
            s = fmaf(K[r * 4 + 1], ext[1 * 4 + c], s);
            s = fmaf(K[r * 4 + 2], ext[2 * 4 + c], s);
            M[r * 4 + c] = s;
        }
#pragma unroll
    for (int c = 0; c < 4; c++) M[12 + c] = ext[12 + c];
}

__device__ void do_setup(const float* pm, int b) {
    float Mr[16], Mi[16];
    make_comb_f32(pm, b, 0, Mr);
    inv4_lapack_f32(Mr, Mi);
    for (int v = 1; v < NV; v++) {
        float Ms[16];
        make_comb_f32(pm, b, v, Ms);
        for (int r = 0; r < 3; r++) {
            for (int c = 0; c < 4; c++) {
                float s = __fmul_rn(Ms[r * 4 + 0], Mi[0 * 4 + c]);
                s = fmaf(Ms[r * 4 + 1], Mi[1 * 4 + c], s);
                s = fmaf(Ms[r * 4 + 2], Mi[2 * 4 + c], s);
                s = fmaf(Ms[r * 4 + 3], Mi[3 * 4 + c], s);
                if (c < 3) g_rot[b][v][r * 3 + c] = s;
                else       g_trans[b][v][r] = s;
            }
        }
    }
}

// ---------------------------------------------------------------------------
// Prep kernel: vectorized feature transpose [V*B, C, HW] -> [V*B, HW, C]
// (float4 on both global sides) + projection setup on 2 threads of block 0.
// Block (8, 32): tx = float4 index, ty = channel (load) / pixel (store).
// ---------------------------------------------------------------------------
__global__ void prep_kernel(const float* __restrict__ fea,
                            const float* __restrict__ pm) {
    __shared__ float tile[32][33];   // [channel][pixel]
    int vb = blockIdx.y;
    int pb = blockIdx.x * 32;
    int tx = threadIdx.x;   // 0..7
    int ty = threadIdx.y;   // 0..31

    if (blockIdx.x == 0 && blockIdx.y == 0 && ty == 31 && tx < NB)
        do_setup(pm, tx);

    // Load: thread (tx,ty) reads 4 pixels of channel ty.
    const float4* src = (const float4*)(fea + ((size_t)vb * NC + ty) * HW + pb);
    float4 v = src[tx];
    tile[ty][4 * tx + 0] = v.x;
    tile[ty][4 * tx + 1] = v.y;
    tile[ty][4 * tx + 2] = v.z;
    tile[ty][4 * tx + 3] = v.w;
    __syncthreads();

    // Store: thread (tx,ty) writes 4 channels of pixel ty.
    float4 o;
    o.x = tile[4 * tx + 0][ty];
    o.y = tile[4 * tx + 1][ty];
    o.z = tile[4 * tx + 2][ty];
    o.w = tile[4 * tx + 3][ty];
    float4* dst = (float4*)((float*)g_featT + ((size_t)vb * HW + pb + ty) * NC);
    dst[tx] = o;
}

__device__ __forceinline__ float warp_bfly_sum(float x) {
    const unsigned FULL = 0xffffffffu;
#pragma unroll
    for (int o = 16; o; o >>= 1) x = __fadd_rn(x, __shfl_xor_sync(FULL, x, o));
    return x;
}

__device__ __forceinline__ float warp_bfly_max(float x) {
    const unsigned FULL = 0xffffffffu;
#pragma unroll
    for (int o = 16; o; o >>= 1) x = fmaxf(x, __shfl_xor_sync(FULL, x, o));
    return x;
}

// Butterfly sum within each 8-lane group (offsets 1,2,4).
__device__ __forceinline__ float group8_sum(float x) {
    const unsigned FULL = 0xffffffffu;
#pragma unroll
    for (int o = 1; o < 8; o <<= 1) x = __fadd_rn(x, __shfl_xor_sync(FULL, x, o));
    return x;
}

// ---------------------------------------------------------------------------
// Main kernel: one warp per ref pixel, lane = depth hypothesis.
// Phase 1: per-view scalars (s, r) with all tap LDGs overlapping.
// Phase 2: softmax accumulation in the frozen sequential-view order.
// ---------------------------------------------------------------------------
__global__ void __launch_bounds__(128, 10) stagenet_main(
    const float* __restrict__ depth_hypo,
    const float* __restrict__ reg_w,
    float* __restrict__ out) {
    const unsigned FULL = 0xffffffffu;
    __shared__ float4 rf_s[4][8];

    int warp = blockIdx.x * (blockDim.x >> 5) + (threadIdx.x >> 5);
    int wslot = threadIdx.x >> 5;
    int lane = threadIdx.x & 31;
    int gl   = lane & 7;

    int b  = warp >> 14;
    int hw = warp & (HW - 1);
    int h  = hw >> 7;
    int w  = hw & (NW - 1);

    if (lane < 8)
        rf_s[wslot][lane] = __ldg(g_featT + ((unsigned)b * HW + hw) * 8 + lane);
    __syncwarp();
    float4 rfl = rf_s[wslot][gl];
    float  rw_l = __ldg(reg_w + gl);

    float dep = depth_hypo[(unsigned)(b * ND + lane) * HW + hw];
    float xw = (float)w, yh = (float)h;

    float s_v[NV - 1], r_v[NV - 1];

#pragma unroll
    for (int vi = 0; vi < NV - 1; vi++) {
        int v = vi + 1;
        const float* R = g_rot[b][v];
        const float* T = g_trans[b][v];
        float rx = fmaf(R[2], 1.f, fmaf(R[1], yh, __fmul_rn(R[0], xw)));
        float ry = fmaf(R[5], 1.f, fmaf(R[4], yh, __fmul_rn(R[3], xw)));
        float rz = fmaf(R[8], 1.f, fmaf(R[7], yh, __fmul_rn(R[6], xw)));
        float X = __fadd_rn(__fmul_rn(rx, dep), T[0]);
        float Y = __fadd_rn(__fmul_rn(ry, dep), T[1]);
        float Z = __fadd_rn(__fmul_rn(rz, dep), T[2]);
        if (Z == 0.f) Z = 1e-9f;
        float px = __fdiv_rn(X, Z);
        float py = __fdiv_rn(Y, Z);

        float x0f = floorf(px), y0f = floorf(py);
        int   x0 = (int)x0f,   y0 = (int)y0f;
        float wx1 = __fsub_rn(px, x0f), wx0 = __fsub_rn(1.f, wx1);
        float wy1 = __fsub_rn(py, y0f), wy0 = __fsub_rn(1.f, wy1);

        int x0c = min(max(x0, 0), NW - 1), x1c = min(max(x0 + 1, 0), NW - 1);
        int y0c = min(max(y0, 0), NH - 1), y1c = min(max(y0 + 1, 0), NH - 1);
        bool vx0 = (x0 >= 0) & (x0 < NW),     vx1 = (x0 + 1 >= 0) & (x0 + 1 < NW);
        bool vy0 = (y0 >= 0) & (y0 < NH),     vy1 = (y0 + 1 >= 0) & (y0 + 1 < NH);
        float wts[4] = {
            (vx0 & vy0) ? __fmul_rn(wx0, wy0) : 0.f,
            (vx1 & vy0) ? __fmul_rn(wx1, wy0) : 0.f,
            (vx0 & vy1) ? __fmul_rn(wx0, wy1) : 0.f,
            (vx1 & vy1) ? __fmul_rn(wx1, wy1) : 0.f };
        const float4* base = g_featT + (unsigned)(v * NB + b) * (HW * 8u);

        bool uni = __all_sync(FULL, x0 == __shfl_sync(FULL, x0, 0)) &&
                   __all_sync(FULL, y0 == __shfl_sync(FULL, y0, 0));

        float s, r;
        if (uni) {
            int xc = (lane & 8)  ? x1c : x0c;
            int yc = (lane & 16) ? y1c : y0c;
            float4 q = __ldg(base + (unsigned)(yc * NW + xc) * 8u + (unsigned)gl);
            float d = fmaf(q.x, rfl.x,
                      fmaf(q.y, rfl.y,
                      fmaf(q.z, rfl.z, __fmul_rn(q.w, rfl.w))));
            float D  = group8_sum(d);                       // sum_g d[t,g]
            float Dr = group8_sum(__fmul_rn(rw_l, d));      // sum_g rw_g*d[t,g]
            float D0  = __shfl_sync(FULL, D, 0),  D1  = __shfl_sync(FULL, D, 8);
            float D2  = __shfl_sync(FULL, D, 16), D3  = __shfl_sync(FULL, D, 24);
            float Dr0 = __shfl_sync(FULL, Dr, 0),  Dr1 = __shfl_sync(FULL, Dr, 8);
            float Dr2 = __shfl_sync(FULL, Dr, 16), Dr3 = __shfl_sync(FULL, Dr, 24);
            s = __fmul_rn(0.25f, fmaf(wts[3], D3, fmaf(wts[2], D2,
                          fmaf(wts[1], D1, __fmul_rn(wts[0], D0)))));
            r = __fmul_rn(0.25f, fmaf(wts[3], Dr3, fmaf(wts[2], Dr2,
                          fmaf(wts[1], Dr1, __fmul_rn(wts[0], Dr0)))));
        } else {
            unsigned off[4] = {
                (unsigned)(y0c * NW + x0c) * 8u,
                (unsigned)(y0c * NW + x1c) * 8u,
                (unsigned)(y1c * NW + x0c) * 8u,
                (unsigned)(y1c * NW + x1c) * 8u };
            float pg[8];
#pragma unroll
            for (int g = 0; g < 8; g++) pg[g] = 0.f;
#pragma unroll
            for (int t = 0; t < 4; t++) {
                float wt = wts[t];
                const float4* tp = base + off[t];
#pragma unroll
                for (int g = 0; g < 8; g++) {
                    float4 q  = __ldg(tp + g);
                    float4 rq = rf_s[wslot][g];
                    float d = fmaf(q.x, rq.x,
                              fmaf(q.y, rq.y,
                              fmaf(q.z, rq.z, __fmul_rn(q.w, rq.w))));
                    pg[g] = fmaf(wt, d, pg[g]);
                }
            }
            s = 0.f; r = 0.f;
#pragma unroll
            for (int g = 0; g < 8; g++) {
                float cfg = __fmul_rn(pg[g], 0.25f);
                float rwg = __shfl_sync(FULL, rw_l, g);
                s = (g == 0) ? cfg : __fadd_rn(s, cfg);
                r = (g == 0) ? __fmul_rn(rwg, cfg) : fmaf(rwg, cfg, r);
            }
        }
        s_v[vi] = s;
        r_v[vi] = r;
    }

    // Phase 2: per-view softmax accumulation (frozen sequential view order).
    float acc_r = 0.f;
    float cw_sum = 1e-8f;
#pragma unroll
    for (int vi = 0; vi < NV - 1; vi++) {
        float s = s_v[vi];
        float m = warp_bfly_max(s);
        float e = expf(__fsub_rn(s, m));
        float es = warp_bfly_sum(e);
        float wv = __fmul_rn(__fdiv_rn(e, es), 0.17677669529663687f);  // 1/sqrt(32)
        cw_sum = __fadd_rn(cw_sum, wv);
        acc_r  = fmaf(wv, r_v[vi], acc_r);
    }

    float logit = __fdiv_rn(acc_r, cw_sum);

    // final softmax over depth
    float m2 = warp_bfly_max(logit);
    float e2 = expf(__fsub_rn(logit, m2));
    float es2 = warp_bfly_sum(e2);
    float attn = __fdiv_rn(e2, es2);

    // outputs: [depth (B*H*W)] then [attn (B*D*H*W)]
    out[(unsigned)NB * HW + (unsigned)(b * ND + lane) * HW + hw] = attn;

    float amax = warp_bfly_max(attn);
    unsigned msk = __ballot_sync(FULL, attn == amax);
    int idx = __ffs(msk) - 1;   // first max, matching jnp.argmax
    if (lane == idx) out[(unsigned)b * HW + hw] = dep;
}

// ---------------------------------------------------------------------------
// Launch
// ---------------------------------------------------------------------------
extern "C" void kernel_launch(void* const* d_in, const int* in_sizes, int n_in,
                              void* d_out, int out_size) {
    const float* features   = (const float*)d_in[0];
    const float* proj       = (const float*)d_in[1];
    const float* depth_hypo = (const float*)d_in[2];
    const float* reg_w      = (const float*)d_in[3];
    float* out = (float*)d_out;

    prep_kernel<<<dim3(HW / 32, NV * NB), dim3(8, 32)>>>(features, proj);
    stagenet_main<<<(NB * HW) / 4, 128>>>(depth_hypo, reg_w, out);
}

// round 14
// speedup vs baseline: 2.7397x; 1.0684x over previous
#include <cuda_runtime.h>
#include <cstdint>

// Problem constants (stagenet_46445776339346): V=5, B=2, C=32, H=W=128, D=32, G=8
#define NV 5
#define NB 2
#define NC 32
#define NH 128
#define NW 128
#define ND 32
#define NG 8
#define HW (NH * NW)

// ---------------------------------------------------------------------------
// Device scratch (no runtime allocation allowed)
// ---------------------------------------------------------------------------
__device__ float  g_rot[NB][NV][9];
__device__ float  g_trans[NB][NV][3];
// features transposed to [V, B, H*W, C]: one bilinear tap = 128 contiguous bytes.
__device__ float4 g_featT[(size_t)NV * NB * HW * (NC / 4)];
// depth hypotheses transposed to [B, H*W, D]: one warp load = 128 contiguous B.
__device__ float  g_depT[(size_t)NB * HW * ND];

// ---------------------------------------------------------------------------
// FROZEN NUMERICS: fp32 4x4 inverse = sgetf2 LU + OpenBLAS-style trsm
// (pre-inverted diagonal). Do not touch.
// ---------------------------------------------------------------------------
__device__ void inv4_lapack_f32(const float* A_rm, float* Ai_rm) {
    float a[16];
    int   piv[4];
#pragma unroll
    for (int r = 0; r < 4; r++)
#pragma unroll
        for (int c = 0; c < 4; c++) a[c * 4 + r] = A_rm[r * 4 + c];

#pragma unroll
    for (int j = 0; j < 4; j++) {
        int jp = j; float amax = fabsf(a[j * 4 + j]);
        for (int i = j + 1; i < 4; i++) {
            float v = fabsf(a[j * 4 + i]);
            if (v > amax) { amax = v; jp = i; }
        }
        piv[j] = jp;
        if (jp != j)
#pragma unroll
            for (int c = 0; c < 4; c++) {
                float t = a[c * 4 + j]; a[c * 4 + j] = a[c * 4 + jp]; a[c * 4 + jp] = t;
            }
        float ainv = __fdiv_rn(1.0f, a[j * 4 + j]);
        for (int i = j + 1; i < 4; i++)
            a[j * 4 + i] = __fmul_rn(a[j * 4 + i], ainv);
        for (int k = j + 1; k < 4; k++) {
            float temp = -a[k * 4 + j];
            for (int i = j + 1; i < 4; i++)
                a[k * 4 + i] = fmaf(a[j * 4 + i], temp, a[k * 4 + i]);
        }
    }

    float dinv[4];
#pragma unroll
    for (int k = 0; k < 4; k++) dinv[k] = __fdiv_rn(1.0f, a[k * 4 + k]);

#pragma unroll
    for (int c = 0; c < 4; c++) {
        float b[4] = {0.f, 0.f, 0.f, 0.f};
        b[c] = 1.0f;
#pragma unroll
        for (int j = 0; j < 4; j++) { float t = b[j]; b[j] = b[piv[j]]; b[piv[j]] = t; }
#pragma unroll
        for (int k = 0; k < 4; k++) {
            float bk = b[k];
            if (bk != 0.f)
                for (int i = k + 1; i < 4; i++)
                    b[i] = fmaf(-bk, a[k * 4 + i], b[i]);
        }
#pragma unroll
        for (int k = 3; k >= 0; k--) {
            b[k] = __fmul_rn(b[k], dinv[k]);
            float bk = b[k];
            for (int i = 0; i < k; i++)
                b[i] = fmaf(-bk, a[k * 4 + i], b[i]);
        }
#pragma unroll
        for (int r = 0; r < 4; r++) Ai_rm[r * 4 + c] = b[r];
    }
}

__device__ void make_comb_f32(const float* pm, int b, int v, float* M) {
    const float* ext = pm + ((size_t)(b * NV + v) * 2 + 0) * 16;
    const float* K   = pm + ((size_t)(b * NV + v) * 2 + 1) * 16;
#pragma unroll
    for (int r = 0; r < 3; r++)
#pragma unroll
        for (int c = 0; c < 4; c++) {
            float s = __fmul_rn(K[r * 4 + 0], ext[0 * 4 + c]);
            s = fmaf(K[r * 4 + 1], ext[1 * 4 + c], s);
            s = fmaf(K[r * 4 + 2], ext[2 * 4 + c], s);
            M[r * 4 + c] = s;
        }
#pragma unroll
    for (int c = 0; c < 4; c++) M[12 + c] = ext[12 + c];
}

__device__ void do_setup(const float* pm, int b) {
    float Mr[16], Mi[16];
    make_comb_f32(pm, b, 0, Mr);
    inv4_lapack_f32(Mr, Mi);
    for (int v = 1; v < NV; v++) {
        float Ms[16];
        make_comb_f32(pm, b, v, Ms);
        for (int r = 0; r < 3; r++) {
            for (int c = 0; c < 4; c++) {
                float s = __fmul_rn(Ms[r * 4 + 0], Mi[0 * 4 + c]);
                s = fmaf(Ms[r * 4 + 1], Mi[1 * 4 + c], s);
                s = fmaf(Ms[r * 4 + 2], Mi[2 * 4 + c], s);
                s = fmaf(Ms[r * 4 + 3], Mi[3 * 4 + c], s);
                if (c < 3) g_rot[b][v][r * 3 + c] = s;
                else       g_trans[b][v][r] = s;
            }
        }
    }
}

// ---------------------------------------------------------------------------
// Prep kernel: 32x32 float4-vectorized transposes.
//   blockIdx.y <  NV*NB : features [C, HW] -> [HW, C]
//   blockIdx.y >= NV*NB : depth    [D, HW] -> [HW, D]   (D == C == 32)
// Projection setup runs on 2 threads of block (0,0), overlapped.
// ---------------------------------------------------------------------------
__global__ void prep_kernel(const float* __restrict__ fea,
                            const float* __restrict__ dh,
                            const float* __restrict__ pm) {
    __shared__ float tile[32][33];
    int by = blockIdx.y;
    int pb = blockIdx.x * 32;
    int tx = threadIdx.x;   // 0..7
    int ty = threadIdx.y;   // 0..31

    if (blockIdx.x == 0 && by == 0 && ty == 31 && tx < NB)
        do_setup(pm, tx);

    const float* src;
    float*       dst;
    if (by < NV * NB) {
        src = fea + ((size_t)by * NC + ty) * HW + pb;
        dst = (float*)g_featT + ((size_t)by * HW + pb) * NC;
    } else {
        int b = by - NV * NB;
        src = dh + ((size_t)b * ND + ty) * HW + pb;
        dst = g_depT + ((size_t)b * HW + pb) * ND;
    }

    float4 v = ((const float4*)src)[tx];
    tile[ty][4 * tx + 0] = v.x;
    tile[ty][4 * tx + 1] = v.y;
    tile[ty][4 * tx + 2] = v.z;
    tile[ty][4 * tx + 3] = v.w;
    __syncthreads();

    float4 o;
    o.x = tile[4 * tx + 0][ty];
    o.y = tile[4 * tx + 1][ty];
    o.z = tile[4 * tx + 2][ty];
    o.w = tile[4 * tx + 3][ty];
    ((float4*)(dst + (size_t)ty * 32))[tx] = o;
}

__device__ __forceinline__ float warp_bfly_sum(float x) {
    const unsigned FULL = 0xffffffffu;
#pragma unroll
    for (int o = 16; o; o >>= 1) x = __fadd_rn(x, __shfl_xor_sync(FULL, x, o));
    return x;
}

__device__ __forceinline__ float warp_bfly_max(float x) {
    const unsigned FULL = 0xffffffffu;
#pragma unroll
    for (int o = 16; o; o >>= 1) x = fmaxf(x, __shfl_xor_sync(FULL, x, o));
    return x;
}

// Butterfly sum within each 8-lane group (offsets 1,2,4).
__device__ __forceinline__ float group8_sum(float x) {
    const unsigned FULL = 0xffffffffu;
#pragma unroll
    for (int o = 1; o < 8; o <<= 1) x = __fadd_rn(x, __shfl_xor_sync(FULL, x, o));
    return x;
}

// ---------------------------------------------------------------------------
// Main kernel: one warp per ref pixel, lane = depth hypothesis.
// Depth load from transposed layout (1 line/warp); attn store staged through
// smem so each warp issues ~8 coalesced transactions instead of 32.
// ---------------------------------------------------------------------------
__global__ void __launch_bounds__(128, 10) stagenet_main(
    const float* __restrict__ reg_w,
    float* __restrict__ out) {
    const unsigned FULL = 0xffffffffu;
    __shared__ float4 rf_s[4][8];
    __shared__ float  attn_s[4][40];   // stride 40: conflict-free both ways

    int warp = blockIdx.x * (blockDim.x >> 5) + (threadIdx.x >> 5);
    int wslot = threadIdx.x >> 5;
    int lane = threadIdx.x & 31;
    int gl   = lane & 7;

    int b  = warp >> 14;
    int hw = warp & (HW - 1);
    int h  = hw >> 7;
    int w  = hw & (NW - 1);

    if (lane < 8)
        rf_s[wslot][lane] = __ldg(g_featT + ((unsigned)b * HW + hw) * 8 + lane);
    __syncwarp();
    float4 rfl = rf_s[wslot][gl];
    float  rw_l = __ldg(reg_w + gl);

    // transposed depth: 32 consecutive floats per warp = 1 cache line
    float dep = g_depT[((unsigned)b * HW + hw) * ND + lane];
    float xw = (float)w, yh = (float)h;

    float s_v[NV - 1], r_v[NV - 1];

#pragma unroll
    for (int vi = 0; vi < NV - 1; vi++) {
        int v = vi + 1;
        const float* R = g_rot[b][v];
        const float* T = g_trans[b][v];
        float rx = fmaf(R[2], 1.f, fmaf(R[1], yh, __fmul_rn(R[0], xw)));
        float ry = fmaf(R[5], 1.f, fmaf(R[4], yh, __fmul_rn(R[3], xw)));
        float rz = fmaf(R[8], 1.f, fmaf(R[7], yh, __fmul_rn(R[6], xw)));
        float X = __fadd_rn(__fmul_rn(rx, dep), T[0]);
        float Y = __fadd_rn(__fmul_rn(ry, dep), T[1]);
        float Z = __fadd_rn(__fmul_rn(rz, dep), T[2]);
        if (Z == 0.f) Z = 1e-9f;
        float px = __fdiv_rn(X, Z);
        float py = __fdiv_rn(Y, Z);

        float x0f = floorf(px), y0f = floorf(py);
        int   x0 = (int)x0f,   y0 = (int)y0f;
        float wx1 = __fsub_rn(px, x0f), wx0 = __fsub_rn(1.f, wx1);
        float wy1 = __fsub_rn(py, y0f), wy0 = __fsub_rn(1.f, wy1);

        int x0c = min(max(x0, 0), NW - 1), x1c = min(max(x0 + 1, 0), NW - 1);
        int y0c = min(max(y0, 0), NH - 1), y1c = min(max(y0 + 1, 0), NH - 1);
        bool vx0 = (x0 >= 0) & (x0 < NW),     vx1 = (x0 + 1 >= 0) & (x0 + 1 < NW);
        bool vy0 = (y0 >= 0) & (y0 < NH),     vy1 = (y0 + 1 >= 0) & (y0 + 1 < NH);
        float wts[4] = {
            (vx0 & vy0) ? __fmul_rn(wx0, wy0) : 0.f,
            (vx1 & vy0) ? __fmul_rn(wx1, wy0) : 0.f,
            (vx0 & vy1) ? __fmul_rn(wx0, wy1) : 0.f,
            (vx1 & vy1) ? __fmul_rn(wx1, wy1) : 0.f };
        const float4* base = g_featT + (unsigned)(v * NB + b) * (HW * 8u);

        bool uni = __all_sync(FULL, x0 == __shfl_sync(FULL, x0, 0)) &&
                   __all_sync(FULL, y0 == __shfl_sync(FULL, y0, 0));

        float s, r;
        if (uni) {
            int xc = (lane & 8)  ? x1c : x0c;
            int yc = (lane & 16) ? y1c : y0c;
            float4 q = __ldg(base + (unsigned)(yc * NW + xc) * 8u + (unsigned)gl);
            float d = fmaf(q.x, rfl.x,
                      fmaf(q.y, rfl.y,
                      fmaf(q.z, rfl.z, __fmul_rn(q.w, rfl.w))));
            float D  = group8_sum(d);                       // sum_g d[t,g]
            float Dr = group8_sum(__fmul_rn(rw_l, d));      // sum_g rw_g*d[t,g]
            float D0  = __shfl_sync(FULL, D, 0),  D1  = __shfl_sync(FULL, D, 8);
            float D2  = __shfl_sync(FULL, D, 16), D3  = __shfl_sync(FULL, D, 24);
            float Dr0 = __shfl_sync(FULL, Dr, 0),  Dr1 = __shfl_sync(FULL, Dr, 8);
            float Dr2 = __shfl_sync(FULL, Dr, 16), Dr3 = __shfl_sync(FULL, Dr, 24);
            s = __fmul_rn(0.25f, fmaf(wts[3], D3, fmaf(wts[2], D2,
                          fmaf(wts[1], D1, __fmul_rn(wts[0], D0)))));
            r = __fmul_rn(0.25f, fmaf(wts[3], Dr3, fmaf(wts[2], Dr2,
                          fmaf(wts[1], Dr1, __fmul_rn(wts[0], Dr0)))));
        } else {
            unsigned off[4] = {
                (unsigned)(y0c * NW + x0c) * 8u,
                (unsigned)(y0c * NW + x1c) * 8u,
                (unsigned)(y1c * NW + x0c) * 8u,
                (unsigned)(y1c * NW + x1c) * 8u };
            float pg[8];
#pragma unroll
            for (int g = 0; g < 8; g++) pg[g] = 0.f;
#pragma unroll
            for (int t = 0; t < 4; t++) {
                float wt = wts[t];
                const float4* tp = base + off[t];
#pragma unroll
                for (int g = 0; g < 8; g++) {
                    float4 q  = __ldg(tp + g);
                    float4 rq = rf_s[wslot][g];
                    float d = fmaf(q.x, rq.x,
                              fmaf(q.y, rq.y,
                              fmaf(q.z, rq.z, __fmul_rn(q.w, rq.w))));
                    pg[g] = fmaf(wt, d, pg[g]);
                }
            }
            s = 0.f; r = 0.f;
#pragma unroll
            for (int g = 0; g < 8; g++) {
                float cfg = __fmul_rn(pg[g], 0.25f);
                float rwg = __shfl_sync(FULL, rw_l, g);
                s = (g == 0) ? cfg : __fadd_rn(s, cfg);
                r = (g == 0) ? __fmul_rn(rwg, cfg) : fmaf(rwg, cfg, r);
            }
        }
        s_v[vi] = s;
        r_v[vi] = r;
    }

    // Per-view softmax accumulation (frozen sequential view order).
    float acc_r = 0.f;
    float cw_sum = 1e-8f;
#pragma unroll
    for (int vi = 0; vi < NV - 1; vi++) {
        float s = s_v[vi];
        float m = warp_bfly_max(s);
        float e = expf(__fsub_rn(s, m));
        float es = warp_bfly_sum(e);
        float wv = __fmul_rn(__fdiv_rn(e, es), 0.17677669529663687f);  // 1/sqrt(32)
        cw_sum = __fadd_rn(cw_sum, wv);
        acc_r  = fmaf(wv, r_v[vi], acc_r);
    }

    float logit = __fdiv_rn(acc_r, cw_sum);

    // final softmax over depth
    float m2 = warp_bfly_max(logit);
    float e2 = expf(__fsub_rn(logit, m2));
    float es2 = warp_bfly_sum(e2);
    float attn = __fdiv_rn(e2, es2);

    // depth output (argmax lane)
    float amax = warp_bfly_max(attn);
    unsigned msk = __ballot_sync(FULL, attn == amax);
    int idx = __ffs(msk) - 1;   // first max, matching jnp.argmax
    if (lane == idx) out[(unsigned)b * HW + hw] = dep;

    // attn output: stage through smem, write coalesced (d-major per block).
    attn_s[wslot][lane] = attn;
    __syncthreads();
    int t = threadIdx.x;
    int d = t >> 2;          // 0..31
    int p = t & 3;           // pixel offset within block
    unsigned hw_base = ((unsigned)blockIdx.x * 4) & (HW - 1);
    out[(unsigned)NB * HW + (unsigned)(b * ND + d) * HW + hw_base + p] =
        attn_s[p][d];
}

// ---------------------------------------------------------------------------
// Launch
// ---------------------------------------------------------------------------
extern "C" void kernel_launch(void* const* d_in, const int* in_sizes, int n_in,
                              void* d_out, int out_size) {
    const float* features   = (const float*)d_in[0];
    const float* proj       = (const float*)d_in[1];
    const float* depth_hypo = (const float*)d_in[2];
    const float* reg_w      = (const float*)d_in[3];
    float* out = (float*)d_out;

    prep_kernel<<<dim3(HW / 32, NV * NB + NB), dim3(8, 32)>>>(features, depth_hypo, proj);
    stagenet_main<<<(NB * HW) / 4, 128>>>(reg_w, out);
}